// round 5
// baseline (speedup 1.0000x reference)
#include <cuda_runtime.h>
#include <cuda_bf16.h>

#define BATCH 4
#define CDIM  256
#define NPIX  4096

// ---------------- device-global scratch (no allocation allowed) ----------------
__device__ float g_WqT [CDIM*CDIM];
__device__ float g_WkT [CDIM*CDIM];
__device__ float g_WdyT[CDIM*CDIM];
__device__ float g_xT  [BATCH*NPIX*CDIM];   // x pixel-major: [b][n][ch]
__device__ float g_qT  [BATCH*NPIX*CDIM];   // q pixel-major
__device__ float g_avT [BATCH*NPIX*CDIM];   // attention output pixel-major
__device__ float g_kctx[BATCH*CDIM*49];
__device__ float g_kf  [BATCH*CDIM*49];     // [(b*256+ch)*49 + l]
__device__ float g_kp  [BATCH*4*74*64];     // [((b*4+g)*74+m)*64 + c]

// ---------------- K0: transpose the three 256x256 weights ----------------
__global__ void __launch_bounds__(256) k0_wt(const float* __restrict__ Wq,
                                             const float* __restrict__ Wk,
                                             const float* __restrict__ Wdy) {
    __shared__ float t[32][33];
    const float* src = (blockIdx.z == 0) ? Wq : ((blockIdx.z == 1) ? Wk : Wdy);
    float* dst = (blockIdx.z == 0) ? g_WqT : ((blockIdx.z == 1) ? g_WkT : g_WdyT);
    int o0 = blockIdx.y * 32, c0 = blockIdx.x * 32;
    int tx = threadIdx.x, ty = threadIdx.y;
#pragma unroll
    for (int r = 0; r < 4; r++)
        t[ty + 8*r][tx] = src[(o0 + ty + 8*r) * 256 + c0 + tx];
    __syncthreads();
#pragma unroll
    for (int r = 0; r < 4; r++)
        dst[(c0 + ty + 8*r) * 256 + o0 + tx] = t[tx][ty + 8*r];
}

// ---------------- K1: x [b][ch][n] -> g_xT [b][n][ch] ----------------
__global__ void __launch_bounds__(256) k1_xt(const float* __restrict__ x) {
    __shared__ float t[32][33];
    int b = blockIdx.z, n0 = blockIdx.x * 32, c0 = blockIdx.y * 32;
    int tx = threadIdx.x, ty = threadIdx.y;
#pragma unroll
    for (int r = 0; r < 4; r++)
        t[ty + 8*r][tx] = x[(b * 256 + c0 + ty + 8*r) * 4096 + n0 + tx];
    __syncthreads();
#pragma unroll
    for (int r = 0; r < 4; r++)
        g_xT[(b * 4096 + n0 + ty + 8*r) * 256 + c0 + tx] = t[tx][ty + 8*r];
}

// ---------------- K2: ctx 8x8 mean pool -> g_kctx [b][c][49] ----------------
__global__ void __launch_bounds__(256) k2_pool(const float* __restrict__ ctx) {
    int idx = blockIdx.x * 256 + threadIdx.x;      // 4*256*49 = 50176 total
    int l = idx % 49;
    int c = (idx / 49) & 255;
    int b = idx / (49 * 256);
    int i = l / 7, j = l % 7;
    const float* base = ctx + ((b * 256 + c) * 56 + i * 8) * 56 + j * 8;
    float s = 0.f;
#pragma unroll
    for (int p = 0; p < 8; p++)
#pragma unroll
        for (int q = 0; q < 8; q++)
            s += base[p * 56 + q];
    g_kctx[idx] = s * (1.f / 64.f);
}

// ---------------- K3: q = LN(Wq @ x) * SCALE, pixel-major out ----------------
__global__ void __launch_bounds__(256) k_qln(const float* __restrict__ x,
                                             const float* __restrict__ gq,
                                             const float* __restrict__ bq) {
    __shared__ float s[256 * 33];
    __shared__ float mu_s[32], rs_s[32];
    const int b = blockIdx.y;
    const int n0 = blockIdx.x * 32;
    const int tid = threadIdx.x;

    for (int idx = tid; idx < 8192; idx += 256) {
        int c = idx >> 5, p = idx & 31;
        s[c * 33 + p] = x[(b * 256 + c) * 4096 + n0 + p];
    }
    __syncthreads();

    float acc[32];
#pragma unroll
    for (int p = 0; p < 32; p++) acc[p] = 0.f;
    for (int c = 0; c < 256; c++) {
        float w = g_WqT[c * 256 + tid];
#pragma unroll
        for (int p = 0; p < 32; p++) acc[p] += w * s[c * 33 + p];
    }
    __syncthreads();
#pragma unroll
    for (int p = 0; p < 32; p++) s[tid * 33 + p] = acc[p];
    __syncthreads();

    // LN stats: warp w handles pixels 4w..4w+3
    {
        int lane = tid & 31;
#pragma unroll
        for (int pp = 0; pp < 4; pp++) {
            int p = (tid >> 5) * 4 + pp;
            float sum = 0.f, sq = 0.f;
#pragma unroll
            for (int r = 0; r < 8; r++) {
                float v = s[(lane + 32 * r) * 33 + p];
                sum += v; sq += v * v;
            }
#pragma unroll
            for (int o = 16; o; o >>= 1) {
                sum += __shfl_xor_sync(0xffffffffu, sum, o);
                sq  += __shfl_xor_sync(0xffffffffu, sq,  o);
            }
            if (lane == 0) {
                float mu = sum * (1.f / 256.f);
                mu_s[p] = mu;
                rs_s[p] = rsqrtf(sq * (1.f / 256.f) - mu * mu + 1e-6f);
            }
        }
    }
    __syncthreads();
    float gg = gq[tid] * 0.125f, bb = bq[tid] * 0.125f;  // SCALE folded in
#pragma unroll
    for (int p = 0; p < 32; p++)
        g_qT[(b * 4096 + n0 + p) * 256 + tid] =
            (s[tid * 33 + p] - mu_s[p]) * rs_s[p] * gg + bb;
}

// ---------------- K4: kf = LN(Wk @ kctx), per (b, l) ----------------
__global__ void __launch_bounds__(256) k_kfln(const float* __restrict__ gk,
                                              const float* __restrict__ bk) {
    __shared__ float kin[256];
    __shared__ float red[16];
    __shared__ float mu_s, rs_s;
    const int l = blockIdx.x, b = blockIdx.y, tid = threadIdx.x;
    kin[tid] = g_kctx[(b * 256 + tid) * 49 + l];
    __syncthreads();
    float acc = 0.f;
    for (int c = 0; c < 256; c++) acc += kin[c] * g_WkT[c * 256 + tid];
    float sum = acc, sq = acc * acc;
#pragma unroll
    for (int o = 16; o; o >>= 1) {
        sum += __shfl_xor_sync(0xffffffffu, sum, o);
        sq  += __shfl_xor_sync(0xffffffffu, sq,  o);
    }
    if ((tid & 31) == 0) { red[tid >> 5] = sum; red[8 + (tid >> 5)] = sq; }
    __syncthreads();
    if (tid == 0) {
        float S = 0.f, Q = 0.f;
#pragma unroll
        for (int w = 0; w < 8; w++) { S += red[w]; Q += red[8 + w]; }
        float mu = S * (1.f / 256.f);
        mu_s = mu;
        rs_s = rsqrtf(Q * (1.f / 256.f) - mu * mu + 1e-6f);
    }
    __syncthreads();
    g_kf[(b * 256 + tid) * 49 + l] = (acc - mu_s) * rs_s * gk[tid] + bk[tid];
}

// ---------------- K5: kp[b,g,m,c] = sum_l Wproj[m,l] * kf[b,g*64+c,l] --------
__global__ void __launch_bounds__(256) k_kp(const float* __restrict__ Wproj) {
    int idx = blockIdx.x * 256 + threadIdx.x;      // 4*4*74*64 = 75776 total
    int c = idx & 63;
    int rest = idx >> 6;
    int m = rest % 74;
    int bg = rest / 74;
    int ch = (bg & 3) * 64 + c;
    int b = bg >> 2;
    const float* kfrow = g_kf + (b * 256 + ch) * 49;
    const float* wrow = Wproj + m * 49;
    float s = 0.f;
#pragma unroll
    for (int l = 0; l < 49; l++) s += wrow[l] * kfrow[l];
    g_kp[idx] = s;
}

// ---------------- K6: logits + rpb + softmax + AV, per (b, g, row) ----------
template <int K>
__global__ void __launch_bounds__(256) k_attn(const float* __restrict__ rpb) {
    constexpr int MK = K * K;
    constexpr int RS = 2 * K - 1;
    constexpr int M0 = (K == 5) ? 0 : 25;
    const int g = blockIdx.y + ((K == 5) ? 0 : 2);
    const int b = blockIdx.z;
    const int i = blockIdx.x;
    const int tid = threadIdx.x;

    __shared__ __align__(16) float uni[7488];   // qs(64x68) + kps(49x64); reused as V stage
    __shared__ float lg[64 * 50];
    __shared__ float rpbs[RS * RS];
    float* qs = uni;
    float* kps = uni + 64 * 68;
    const int bn = b * 4096;

    // -------- phase 1 loads --------
    for (int idx = tid; idx < 64 * 16; idx += 256) {
        int j = idx >> 4, cc = idx & 15;
        *(float4*)&qs[j * 68 + cc * 4] =
            *(const float4*)&g_qT[(bn + i * 64 + j) * 256 + g * 64 + cc * 4];
    }
    const float* kpbase = g_kp + ((b * 4 + g) * 74 + M0) * 64;
    for (int idx = tid; idx < MK * 16; idx += 256)
        *(float4*)&kps[idx * 4] = *(const float4*)&kpbase[idx * 4];
    for (int idx = tid; idx < RS * RS; idx += 256)
        rpbs[idx] = rpb[(g & 1) * RS * RS + idx];
    __syncthreads();

    // -------- logits: wgt[j][m] = sum_c q[j][c] * kp[m][c] --------
    {
        int j = tid & 63, mslot = tid >> 6;
        float4 qv[16];
#pragma unroll
        for (int cc = 0; cc < 16; cc++) qv[cc] = *(float4*)&qs[j * 68 + cc * 4];
        for (int m = mslot; m < MK; m += 4) {
            float a = 0.f;
#pragma unroll
            for (int cc = 0; cc < 16; cc++) {
                float4 kv = *(float4*)&kps[m * 64 + cc * 4];   // broadcast across warp
                a += qv[cc].x * kv.x + qv[cc].y * kv.y + qv[cc].z * kv.z + qv[cc].w * kv.w;
            }
            lg[j * 50 + m] = a;
        }
    }
    __syncthreads();

    // -------- rpb + softmax (4 lanes per j, disjoint m sets) --------
    const int si = min(max(i - K / 2, 0), 64 - K);
    const int j2 = tid >> 2, sub = tid & 3;
    const int sj = min(max(j2 - K / 2, 0), 64 - K);
    {
        int ro = (K - 1) - (i - si);
        int co = (K - 1) - (j2 - sj);
        float mx = -1e30f;
        for (int m = sub; m < MK; m += 4) {
            int p = m / K, q = m - p * K;
            float v = lg[j2 * 50 + m] + rpbs[(ro + p) * RS + (co + q)];
            lg[j2 * 50 + m] = v;
            mx = fmaxf(mx, v);
        }
        mx = fmaxf(mx, __shfl_xor_sync(0xffffffffu, mx, 1));
        mx = fmaxf(mx, __shfl_xor_sync(0xffffffffu, mx, 2));
        float s = 0.f;
        for (int m = sub; m < MK; m += 4) {
            float e = __expf(lg[j2 * 50 + m] - mx);
            lg[j2 * 50 + m] = e;
            s += e;
        }
        s += __shfl_xor_sync(0xffffffffu, s, 1);
        s += __shfl_xor_sync(0xffffffffu, s, 2);
        float inv = 1.f / s;
        for (int m = sub; m < MK; m += 4) lg[j2 * 50 + m] *= inv;
    }

    // -------- AV: channel quarters, V staged in smem (reuses qs/kps) --------
    float4* vs4 = (float4*)uni;
    for (int cq = 0; cq < 4; cq++) {
        __syncthreads();
        for (int idx = tid; idx < K * 64 * 4; idx += 256) {
            int p = idx >> 8, col = (idx >> 2) & 63, c4 = idx & 3;
            vs4[idx] = *(const float4*)&g_xT[(bn + (si + p) * 64 + col) * 256 +
                                             g * 64 + cq * 16 + c4 * 4];
        }
        __syncthreads();
        float4 acc = make_float4(0.f, 0.f, 0.f, 0.f);
#pragma unroll
        for (int p = 0; p < K; p++)
#pragma unroll
            for (int q = 0; q < K; q++) {
                float a = lg[j2 * 50 + p * K + q];
                float4 v = vs4[(p * 64 + sj + q) * 4 + sub];
                acc.x += a * v.x; acc.y += a * v.y;
                acc.z += a * v.z; acc.w += a * v.w;
            }
        *(float4*)&g_avT[(bn + i * 64 + j2) * 256 + g * 64 + cq * 16 + sub * 4] = acc;
    }
}

// ---------------- K7: out = BN(Wdy @ av), channel-major output ----------------
__global__ void __launch_bounds__(256) k_out(float* __restrict__ out,
                                             const float* __restrict__ bn_g,
                                             const float* __restrict__ bn_b) {
    __shared__ float s[32 * 257];
    const int b = blockIdx.y, n0 = blockIdx.x * 32, tid = threadIdx.x;

    for (int idx = tid; idx < 2048; idx += 256) {
        int p = idx >> 6, c4 = idx & 63;
        float4 v = *(const float4*)&g_avT[(b * 4096 + n0 + p) * 256 + c4 * 4];
        s[p * 257 + c4 * 4 + 0] = v.x;
        s[p * 257 + c4 * 4 + 1] = v.y;
        s[p * 257 + c4 * 4 + 2] = v.z;
        s[p * 257 + c4 * 4 + 3] = v.w;
    }
    __syncthreads();

    float acc[32];
#pragma unroll
    for (int p = 0; p < 32; p++) acc[p] = 0.f;
    for (int c = 0; c < 256; c++) {
        float w = g_WdyT[c * 256 + tid];
#pragma unroll
        for (int p = 0; p < 32; p++) acc[p] += w * s[p * 257 + c];
    }
    float gsc = bn_g[tid] * rsqrtf(1.f + 1e-5f);
    float bsc = bn_b[tid];
    __syncthreads();
#pragma unroll
    for (int p = 0; p < 32; p++) s[p * 257 + tid] = acc[p] * gsc + bsc;
    __syncthreads();
#pragma unroll
    for (int rep = 0; rep < 32; rep++) {
        int o = rep * 8 + (tid >> 5), p = tid & 31;
        out[(b * 256 + o) * 4096 + n0 + p] = s[p * 257 + o];
    }
}

// ---------------- launch ----------------
extern "C" void kernel_launch(void* const* d_in, const int* in_sizes, int n_in,
                              void* d_out, int out_size) {
    const float* x     = (const float*)d_in[0];
    const float* ctx   = (const float*)d_in[1];
    const float* Wq    = (const float*)d_in[2];
    const float* gq    = (const float*)d_in[3];
    const float* bq    = (const float*)d_in[4];
    const float* Wk    = (const float*)d_in[5];
    const float* gk    = (const float*)d_in[6];
    const float* bk    = (const float*)d_in[7];
    const float* Wproj = (const float*)d_in[8];
    const float* rpb1  = (const float*)d_in[9];
    const float* rpb2  = (const float*)d_in[10];
    const float* Wdy   = (const float*)d_in[11];
    const float* bn_g  = (const float*)d_in[12];
    const float* bn_b  = (const float*)d_in[13];
    float* out = (float*)d_out;

    dim3 b32(32, 8);
    k0_wt  <<<dim3(8, 8, 3),   b32>>>(Wq, Wk, Wdy);
    k1_xt  <<<dim3(128, 8, 4), b32>>>(x);
    k2_pool<<<196, 256>>>(ctx);
    k_qln  <<<dim3(128, 4), 256>>>(x, gq, bq);
    k_kfln <<<dim3(49, 4),  256>>>(gk, bk);
    k_kp   <<<296, 256>>>(Wproj);
    k_attn<5><<<dim3(64, 2, 4), 256>>>(rpb1);
    k_attn<7><<<dim3(64, 2, 4), 256>>>(rpb2);
    k_out  <<<dim3(128, 4), 256>>>(out, bn_g, bn_b);
}

// round 6
// speedup vs baseline: 1.5061x; 1.5061x over previous
#include <cuda_runtime.h>
#include <cuda_bf16.h>

#define BATCH 4
#define CDIM  256
#define NPIX  4096

// ---------------- device-global scratch (no allocation allowed) ----------------
__device__ float g_WqT [CDIM*CDIM];
__device__ float g_WkT [CDIM*CDIM];
__device__ float g_WdyT[CDIM*CDIM];
__device__ float g_xT  [BATCH*NPIX*CDIM];   // x pixel-major: [b][n][ch]
__device__ float g_qT  [BATCH*NPIX*CDIM];   // q pixel-major
__device__ float g_avT [BATCH*NPIX*CDIM];   // attention output pixel-major
__device__ float g_kctx[BATCH*CDIM*49];
__device__ float g_kf  [BATCH*CDIM*49];     // [(b*256+ch)*49 + l]
__device__ float g_kp  [BATCH*4*74*64];     // [((b*4+g)*74+m)*64 + c]

// ---------------- K0: transpose the three 256x256 weights ----------------
__global__ void __launch_bounds__(256) k0_wt(const float* __restrict__ Wq,
                                             const float* __restrict__ Wk,
                                             const float* __restrict__ Wdy) {
    __shared__ float t[32][33];
    const float* src = (blockIdx.z == 0) ? Wq : ((blockIdx.z == 1) ? Wk : Wdy);
    float* dst = (blockIdx.z == 0) ? g_WqT : ((blockIdx.z == 1) ? g_WkT : g_WdyT);
    int o0 = blockIdx.y * 32, c0 = blockIdx.x * 32;
    int tx = threadIdx.x, ty = threadIdx.y;
#pragma unroll
    for (int r = 0; r < 4; r++)
        t[ty + 8*r][tx] = src[(o0 + ty + 8*r) * 256 + c0 + tx];
    __syncthreads();
#pragma unroll
    for (int r = 0; r < 4; r++)
        dst[(c0 + ty + 8*r) * 256 + o0 + tx] = t[tx][ty + 8*r];
}

// ---------------- K1: x [b][ch][n] -> g_xT [b][n][ch] ----------------
__global__ void __launch_bounds__(256) k1_xt(const float* __restrict__ x) {
    __shared__ float t[32][33];
    int b = blockIdx.z, n0 = blockIdx.x * 32, c0 = blockIdx.y * 32;
    int tx = threadIdx.x, ty = threadIdx.y;
#pragma unroll
    for (int r = 0; r < 4; r++)
        t[ty + 8*r][tx] = x[(b * 256 + c0 + ty + 8*r) * 4096 + n0 + tx];
    __syncthreads();
#pragma unroll
    for (int r = 0; r < 4; r++)
        g_xT[(b * 4096 + n0 + ty + 8*r) * 256 + c0 + tx] = t[tx][ty + 8*r];
}

// ---------------- K2: ctx 8x8 mean pool -> g_kctx [b][c][49] ----------------
__global__ void __launch_bounds__(256) k2_pool(const float* __restrict__ ctx) {
    int idx = blockIdx.x * 256 + threadIdx.x;      // 4*256*49 = 50176 total
    int l = idx % 49;
    int c = (idx / 49) & 255;
    int b = idx / (49 * 256);
    int i = l / 7, j = l % 7;
    const float* base = ctx + ((b * 256 + c) * 56 + i * 8) * 56 + j * 8;
    float s = 0.f;
#pragma unroll
    for (int p = 0; p < 8; p++)
#pragma unroll
        for (int q = 0; q < 8; q++)
            s += base[p * 56 + q];
    g_kctx[idx] = s * (1.f / 64.f);
}

// ============ K3: q = LN(Wq @ x) * SCALE — register-tiled GEMM + fused LN ======
// Block: 256 out-ch x 32 px. Thread tile: 4 o x 8 n. BK=16.
__global__ void __launch_bounds__(256) k_qln(const float* __restrict__ x,
                                             const float* __restrict__ gq,
                                             const float* __restrict__ bq) {
    __shared__ __align__(16) float ubuf[32 * 260];   // GEMM tiles / LN stage union
    __shared__ float mu_s[32], rs_s[32];
    float* s_w = ubuf;                // [16][256]
    float* s_x = ubuf + 4096;         // [16][36]
    const int b = blockIdx.y;
    const int n0 = blockIdx.x * 32;
    const int tid = threadIdx.x;
    const int oq = (tid & 63) * 4;
    const int nq = (tid >> 6) * 8;

    float4 gg = *(const float4*)&gq[oq];
    float4 bb = *(const float4*)&bq[oq];

    float acc[4][8];
#pragma unroll
    for (int oi = 0; oi < 4; oi++)
#pragma unroll
        for (int ni = 0; ni < 8; ni++) acc[oi][ni] = 0.f;

    for (int c0 = 0; c0 < 256; c0 += 16) {
        __syncthreads();
        // W tile: 16x256 floats = 1024 float4
        for (int t = tid; t < 1024; t += 256) {
            int k = t >> 6, o = (t & 63) * 4;
            *(float4*)&s_w[k * 256 + o] = *(const float4*)&g_WqT[(c0 + k) * 256 + o];
        }
        // X tile: 16x32 floats = 128 float4 (x is channel-major)
        if (tid < 128) {
            int k = tid >> 3, nn = (tid & 7) * 4;
            *(float4*)&s_x[k * 36 + nn] =
                *(const float4*)&x[(b * 256 + c0 + k) * 4096 + n0 + nn];
        }
        __syncthreads();
#pragma unroll
        for (int k = 0; k < 16; k++) {
            float4 w  = *(float4*)&s_w[k * 256 + oq];
            float4 x0 = *(float4*)&s_x[k * 36 + nq];
            float4 x1 = *(float4*)&s_x[k * 36 + nq + 4];
            float xs[8] = {x0.x, x0.y, x0.z, x0.w, x1.x, x1.y, x1.z, x1.w};
            float ws[4] = {w.x, w.y, w.z, w.w};
#pragma unroll
            for (int oi = 0; oi < 4; oi++)
#pragma unroll
                for (int ni = 0; ni < 8; ni++)
                    acc[oi][ni] += ws[oi] * xs[ni];
        }
    }
    __syncthreads();

    // Stage to smem n-major [32][260] for LN stats (STS.128 conflict-free)
#pragma unroll
    for (int ni = 0; ni < 8; ni++) {
        float4 v = make_float4(acc[0][ni], acc[1][ni], acc[2][ni], acc[3][ni]);
        *(float4*)&ubuf[(nq + ni) * 260 + oq] = v;
    }
    __syncthreads();

    // Stats: warp w handles pixels 4w..4w+3
    {
        int lane = tid & 31;
#pragma unroll
        for (int pp = 0; pp < 4; pp++) {
            int p = (tid >> 5) * 4 + pp;
            float sum = 0.f, sq = 0.f;
#pragma unroll
            for (int r = 0; r < 8; r++) {
                float v = ubuf[p * 260 + lane + 32 * r];
                sum += v; sq += v * v;
            }
#pragma unroll
            for (int o = 16; o; o >>= 1) {
                sum += __shfl_xor_sync(0xffffffffu, sum, o);
                sq  += __shfl_xor_sync(0xffffffffu, sq,  o);
            }
            if (lane == 0) {
                float mu = sum * (1.f / 256.f);
                mu_s[p] = mu;
                rs_s[p] = rsqrtf(sq * (1.f / 256.f) - mu * mu + 1e-6f);
            }
        }
    }
    __syncthreads();

    const int bn = b * 4096;
    float gs[4] = {gg.x * 0.125f, gg.y * 0.125f, gg.z * 0.125f, gg.w * 0.125f};
    float bs[4] = {bb.x * 0.125f, bb.y * 0.125f, bb.z * 0.125f, bb.w * 0.125f};
#pragma unroll
    for (int ni = 0; ni < 8; ni++) {
        float mu = mu_s[nq + ni], rs = rs_s[nq + ni];
        float4 v;
        v.x = (acc[0][ni] - mu) * rs * gs[0] + bs[0];
        v.y = (acc[1][ni] - mu) * rs * gs[1] + bs[1];
        v.z = (acc[2][ni] - mu) * rs * gs[2] + bs[2];
        v.w = (acc[3][ni] - mu) * rs * gs[3] + bs[3];
        *(float4*)&g_qT[(bn + n0 + nq + ni) * 256 + oq] = v;
    }
}

// ---------------- K4: kf = LN(Wk @ kctx), per (b, l) ----------------
__global__ void __launch_bounds__(256) k_kfln(const float* __restrict__ gk,
                                              const float* __restrict__ bk) {
    __shared__ float kin[256];
    __shared__ float red[16];
    __shared__ float mu_s, rs_s;
    const int l = blockIdx.x, b = blockIdx.y, tid = threadIdx.x;
    kin[tid] = g_kctx[(b * 256 + tid) * 49 + l];
    __syncthreads();
    float acc = 0.f;
    for (int c = 0; c < 256; c++) acc += kin[c] * g_WkT[c * 256 + tid];
    float sum = acc, sq = acc * acc;
#pragma unroll
    for (int o = 16; o; o >>= 1) {
        sum += __shfl_xor_sync(0xffffffffu, sum, o);
        sq  += __shfl_xor_sync(0xffffffffu, sq,  o);
    }
    if ((tid & 31) == 0) { red[tid >> 5] = sum; red[8 + (tid >> 5)] = sq; }
    __syncthreads();
    if (tid == 0) {
        float S = 0.f, Q = 0.f;
#pragma unroll
        for (int w = 0; w < 8; w++) { S += red[w]; Q += red[8 + w]; }
        float mu = S * (1.f / 256.f);
        mu_s = mu;
        rs_s = rsqrtf(Q * (1.f / 256.f) - mu * mu + 1e-6f);
    }
    __syncthreads();
    g_kf[(b * 256 + tid) * 49 + l] = (acc - mu_s) * rs_s * gk[tid] + bk[tid];
}

// ---------------- K5: kp[b,g,m,c] = sum_l Wproj[m,l] * kf[b,g*64+c,l] --------
__global__ void __launch_bounds__(256) k_kp(const float* __restrict__ Wproj) {
    int idx = blockIdx.x * 256 + threadIdx.x;      // 4*4*74*64 = 75776 total
    int c = idx & 63;
    int rest = idx >> 6;
    int m = rest % 74;
    int bg = rest / 74;
    int ch = (bg & 3) * 64 + c;
    int b = bg >> 2;
    const float* kfrow = g_kf + (b * 256 + ch) * 49;
    const float* wrow = Wproj + m * 49;
    float s = 0.f;
#pragma unroll
    for (int l = 0; l < 49; l++) s += wrow[l] * kfrow[l];
    g_kp[idx] = s;
}

// ---------------- K6: logits + rpb + softmax + AV, per (b, g, row) ----------
template <int K>
__global__ void __launch_bounds__(256) k_attn(const float* __restrict__ rpb) {
    constexpr int MK = K * K;
    constexpr int RS = 2 * K - 1;
    constexpr int M0 = (K == 5) ? 0 : 25;
    const int g = blockIdx.y + ((K == 5) ? 0 : 2);
    const int b = blockIdx.z;
    const int i = blockIdx.x;
    const int tid = threadIdx.x;

    __shared__ __align__(16) float uni[7488];   // qs(64x68) + kps(49x64); reused as V stage
    __shared__ float lg[64 * 50];
    __shared__ float rpbs[RS * RS];
    float* qs = uni;
    float* kps = uni + 64 * 68;
    const int bn = b * 4096;

    // -------- phase 1 loads --------
    for (int idx = tid; idx < 64 * 16; idx += 256) {
        int j = idx >> 4, cc = idx & 15;
        *(float4*)&qs[j * 68 + cc * 4] =
            *(const float4*)&g_qT[(bn + i * 64 + j) * 256 + g * 64 + cc * 4];
    }
    const float* kpbase = g_kp + ((b * 4 + g) * 74 + M0) * 64;
    for (int idx = tid; idx < MK * 16; idx += 256)
        *(float4*)&kps[idx * 4] = *(const float4*)&kpbase[idx * 4];
    for (int idx = tid; idx < RS * RS; idx += 256)
        rpbs[idx] = rpb[(g & 1) * RS * RS + idx];
    __syncthreads();

    // -------- logits: wgt[j][m] = sum_c q[j][c] * kp[m][c] --------
    {
        int j = tid & 63, mslot = tid >> 6;
        float4 qv[16];
#pragma unroll
        for (int cc = 0; cc < 16; cc++) qv[cc] = *(float4*)&qs[j * 68 + cc * 4];
        for (int m = mslot; m < MK; m += 4) {
            float a = 0.f;
#pragma unroll
            for (int cc = 0; cc < 16; cc++) {
                float4 kv = *(float4*)&kps[m * 64 + cc * 4];   // broadcast across warp
                a += qv[cc].x * kv.x + qv[cc].y * kv.y + qv[cc].z * kv.z + qv[cc].w * kv.w;
            }
            lg[j * 50 + m] = a;
        }
    }
    __syncthreads();

    // -------- rpb + softmax (4 lanes per j, disjoint m sets) --------
    const int si = min(max(i - K / 2, 0), 64 - K);
    const int j2 = tid >> 2, sub = tid & 3;
    const int sj = min(max(j2 - K / 2, 0), 64 - K);
    {
        int ro = (K - 1) - (i - si);
        int co = (K - 1) - (j2 - sj);
        float mx = -1e30f;
        for (int m = sub; m < MK; m += 4) {
            int p = m / K, q = m - p * K;
            float v = lg[j2 * 50 + m] + rpbs[(ro + p) * RS + (co + q)];
            lg[j2 * 50 + m] = v;
            mx = fmaxf(mx, v);
        }
        mx = fmaxf(mx, __shfl_xor_sync(0xffffffffu, mx, 1));
        mx = fmaxf(mx, __shfl_xor_sync(0xffffffffu, mx, 2));
        float s = 0.f;
        for (int m = sub; m < MK; m += 4) {
            float e = __expf(lg[j2 * 50 + m] - mx);
            lg[j2 * 50 + m] = e;
            s += e;
        }
        s += __shfl_xor_sync(0xffffffffu, s, 1);
        s += __shfl_xor_sync(0xffffffffu, s, 2);
        float inv = 1.f / s;
        for (int m = sub; m < MK; m += 4) lg[j2 * 50 + m] *= inv;
    }

    // -------- AV: channel quarters, V staged in smem (reuses qs/kps) --------
    float4* vs4 = (float4*)uni;
    for (int cq = 0; cq < 4; cq++) {
        __syncthreads();
        for (int idx = tid; idx < K * 64 * 4; idx += 256) {
            int p = idx >> 8, col = (idx >> 2) & 63, c4 = idx & 3;
            vs4[idx] = *(const float4*)&g_xT[(bn + (si + p) * 64 + col) * 256 +
                                             g * 64 + cq * 16 + c4 * 4];
        }
        __syncthreads();
        float4 acc = make_float4(0.f, 0.f, 0.f, 0.f);
#pragma unroll
        for (int p = 0; p < K; p++)
#pragma unroll
            for (int q = 0; q < K; q++) {
                float a = lg[j2 * 50 + p * K + q];
                float4 v = vs4[(p * 64 + sj + q) * 4 + sub];
                acc.x += a * v.x; acc.y += a * v.y;
                acc.z += a * v.z; acc.w += a * v.w;
            }
        *(float4*)&g_avT[(bn + i * 64 + j2) * 256 + g * 64 + cq * 16 + sub * 4] = acc;
    }
}

// ============ K7: out = BN(Wdy @ av) — register-tiled GEMM, channel-major out ==
__global__ void __launch_bounds__(256) k_out(float* __restrict__ out,
                                             const float* __restrict__ bn_g,
                                             const float* __restrict__ bn_b) {
    __shared__ __align__(16) float s_w[16 * 256];
    __shared__ __align__(16) float s_x[16 * 36];
    const int b = blockIdx.y;
    const int n0 = blockIdx.x * 32;
    const int tid = threadIdx.x;
    const int oq = (tid & 63) * 4;
    const int nq = (tid >> 6) * 8;
    const int bn = b * 4096;

    float acc[4][8];
#pragma unroll
    for (int oi = 0; oi < 4; oi++)
#pragma unroll
        for (int ni = 0; ni < 8; ni++) acc[oi][ni] = 0.f;

    for (int c0 = 0; c0 < 256; c0 += 16) {
        __syncthreads();
        for (int t = tid; t < 1024; t += 256) {
            int k = t >> 6, o = (t & 63) * 4;
            *(float4*)&s_w[k * 256 + o] = *(const float4*)&g_WdyT[(c0 + k) * 256 + o];
        }
        // X tile from pixel-major g_avT: transpose on store
        if (tid < 128) {
            int n = tid >> 2, c4 = tid & 3;
            float4 v = *(const float4*)&g_avT[(bn + n0 + n) * 256 + c0 + c4 * 4];
            s_x[(c4 * 4 + 0) * 36 + n] = v.x;
            s_x[(c4 * 4 + 1) * 36 + n] = v.y;
            s_x[(c4 * 4 + 2) * 36 + n] = v.z;
            s_x[(c4 * 4 + 3) * 36 + n] = v.w;
        }
        __syncthreads();
#pragma unroll
        for (int k = 0; k < 16; k++) {
            float4 w  = *(float4*)&s_w[k * 256 + oq];
            float4 x0 = *(float4*)&s_x[k * 36 + nq];
            float4 x1 = *(float4*)&s_x[k * 36 + nq + 4];
            float xs[8] = {x0.x, x0.y, x0.z, x0.w, x1.x, x1.y, x1.z, x1.w};
            float ws[4] = {w.x, w.y, w.z, w.w};
#pragma unroll
            for (int oi = 0; oi < 4; oi++)
#pragma unroll
                for (int ni = 0; ni < 8; ni++)
                    acc[oi][ni] += ws[oi] * xs[ni];
        }
    }

    const float rinv = rsqrtf(1.f + 1e-5f);
    float4 g4 = *(const float4*)&bn_g[oq];
    float4 b4 = *(const float4*)&bn_b[oq];
    float gsc[4] = {g4.x * rinv, g4.y * rinv, g4.z * rinv, g4.w * rinv};
    float bsc[4] = {b4.x, b4.y, b4.z, b4.w};
#pragma unroll
    for (int oi = 0; oi < 4; oi++) {
        float4 v0, v1;
        v0.x = acc[oi][0] * gsc[oi] + bsc[oi];
        v0.y = acc[oi][1] * gsc[oi] + bsc[oi];
        v0.z = acc[oi][2] * gsc[oi] + bsc[oi];
        v0.w = acc[oi][3] * gsc[oi] + bsc[oi];
        v1.x = acc[oi][4] * gsc[oi] + bsc[oi];
        v1.y = acc[oi][5] * gsc[oi] + bsc[oi];
        v1.z = acc[oi][6] * gsc[oi] + bsc[oi];
        v1.w = acc[oi][7] * gsc[oi] + bsc[oi];
        float* dst = out + (b * 256 + oq + oi) * 4096 + n0 + nq;
        *(float4*)dst = v0;
        *(float4*)(dst + 4) = v1;
    }
}

// ---------------- launch ----------------
extern "C" void kernel_launch(void* const* d_in, const int* in_sizes, int n_in,
                              void* d_out, int out_size) {
    const float* x     = (const float*)d_in[0];
    const float* ctx   = (const float*)d_in[1];
    const float* Wq    = (const float*)d_in[2];
    const float* gq    = (const float*)d_in[3];
    const float* bq    = (const float*)d_in[4];
    const float* Wk    = (const float*)d_in[5];
    const float* gk    = (const float*)d_in[6];
    const float* bk    = (const float*)d_in[7];
    const float* Wproj = (const float*)d_in[8];
    const float* rpb1  = (const float*)d_in[9];
    const float* rpb2  = (const float*)d_in[10];
    const float* Wdy   = (const float*)d_in[11];
    const float* bn_g  = (const float*)d_in[12];
    const float* bn_b  = (const float*)d_in[13];
    float* out = (float*)d_out;

    dim3 b32(32, 8);
    k0_wt  <<<dim3(8, 8, 3),   b32>>>(Wq, Wk, Wdy);
    k1_xt  <<<dim3(128, 8, 4), b32>>>(x);
    k2_pool<<<196, 256>>>(ctx);
    k_qln  <<<dim3(128, 4), 256>>>(x, gq, bq);
    k_kfln <<<dim3(49, 4),  256>>>(gk, bk);
    k_kp   <<<296, 256>>>(Wproj);
    k_attn<5><<<dim3(64, 2, 4), 256>>>(rpb1);
    k_attn<7><<<dim3(64, 2, 4), 256>>>(rpb2);
    k_out  <<<dim3(128, 4), 256>>>(out, bn_g, bn_b);
}

// round 7
// speedup vs baseline: 1.9849x; 1.3179x over previous
#include <cuda_runtime.h>
#include <cuda_bf16.h>

#define BATCH 4
#define CDIM  256
#define NPIX  4096

typedef unsigned long long ull;

// ---------------- device-global scratch (no allocation allowed) ----------------
__device__ float g_WqT [CDIM*CDIM];
__device__ float g_WkT [CDIM*CDIM];
__device__ float g_WdyT[CDIM*CDIM];
__device__ float g_xT  [BATCH*NPIX*CDIM];   // x pixel-major: [b][n][ch]
__device__ float g_qT  [BATCH*NPIX*CDIM];   // q pixel-major
__device__ float g_avT [BATCH*NPIX*CDIM];   // attention output pixel-major
__device__ float g_kctx[BATCH*CDIM*49];
__device__ float g_kf  [BATCH*CDIM*49];     // [(b*256+ch)*49 + l]
__device__ float g_kp  [BATCH*4*74*64];     // [((b*4+g)*74+m)*64 + c]

// ---------------- f32x2 helpers ----------------
__device__ __forceinline__ void ffma2(ull& d, ull a, ull b) {
    asm("fma.rn.f32x2 %0, %1, %2, %0;" : "+l"(d) : "l"(a), "l"(b));
}
__device__ __forceinline__ ull pack2(float lo, float hi) {
    ull r; asm("mov.b64 %0, {%1, %2};" : "=l"(r) : "f"(lo), "f"(hi)); return r;
}
__device__ __forceinline__ float2 unpack2(ull v) {
    float2 r; asm("mov.b64 {%0, %1}, %2;" : "=f"(r.x), "=f"(r.y) : "l"(v)); return r;
}
__device__ __forceinline__ void cp16(void* smem, const void* gmem) {
    unsigned s = (unsigned)__cvta_generic_to_shared(smem);
    asm volatile("cp.async.cg.shared.global [%0], [%1], 16;\n" :: "r"(s), "l"(gmem));
}
#define CP_COMMIT() asm volatile("cp.async.commit_group;\n" ::: "memory")
#define CP_WAIT0()  asm volatile("cp.async.wait_group 0;\n" ::: "memory")

// ---------------- K0: transpose the three 256x256 weights ----------------
__global__ void __launch_bounds__(256) k0_wt(const float* __restrict__ Wq,
                                             const float* __restrict__ Wk,
                                             const float* __restrict__ Wdy) {
    __shared__ float t[32][33];
    const float* src = (blockIdx.z == 0) ? Wq : ((blockIdx.z == 1) ? Wk : Wdy);
    float* dst = (blockIdx.z == 0) ? g_WqT : ((blockIdx.z == 1) ? g_WkT : g_WdyT);
    int o0 = blockIdx.y * 32, c0 = blockIdx.x * 32;
    int tx = threadIdx.x, ty = threadIdx.y;
#pragma unroll
    for (int r = 0; r < 4; r++)
        t[ty + 8*r][tx] = src[(o0 + ty + 8*r) * 256 + c0 + tx];
    __syncthreads();
#pragma unroll
    for (int r = 0; r < 4; r++)
        dst[(c0 + ty + 8*r) * 256 + o0 + tx] = t[tx][ty + 8*r];
}

// ---------------- K1: x [b][ch][n] -> g_xT [b][n][ch] ----------------
__global__ void __launch_bounds__(256) k1_xt(const float* __restrict__ x) {
    __shared__ float t[32][33];
    int b = blockIdx.z, n0 = blockIdx.x * 32, c0 = blockIdx.y * 32;
    int tx = threadIdx.x, ty = threadIdx.y;
#pragma unroll
    for (int r = 0; r < 4; r++)
        t[ty + 8*r][tx] = x[(b * 256 + c0 + ty + 8*r) * 4096 + n0 + tx];
    __syncthreads();
#pragma unroll
    for (int r = 0; r < 4; r++)
        g_xT[(b * 4096 + n0 + ty + 8*r) * 256 + c0 + tx] = t[tx][ty + 8*r];
}

// ---------------- K2: ctx 8x8 mean pool -> g_kctx [b][c][49] ----------------
__global__ void __launch_bounds__(256) k2_pool(const float* __restrict__ ctx) {
    int idx = blockIdx.x * 256 + threadIdx.x;
    int l = idx % 49;
    int c = (idx / 49) & 255;
    int b = idx / (49 * 256);
    int i = l / 7, j = l % 7;
    const float* base = ctx + ((b * 256 + c) * 56 + i * 8) * 56 + j * 8;
    float s = 0.f;
#pragma unroll
    for (int p = 0; p < 8; p++)
#pragma unroll
        for (int q = 0; q < 8; q++)
            s += base[p * 56 + q];
    g_kctx[idx] = s * (1.f / 64.f);
}

// ======== K3: q = LN(Wq @ x) * SCALE — f32x2 GEMM 256o x 64n, cp.async DB ======
__global__ void __launch_bounds__(256) k_qln(const float* __restrict__ x,
                                             const float* __restrict__ gq,
                                             const float* __restrict__ bq) {
    __shared__ __align__(16) float s_w[2][16 * 256];
    __shared__ __align__(16) float s_x[2][16 * 64];
    const int b = blockIdx.y, n0 = blockIdx.x * 64, tid = threadIdx.x;
    const int lane = tid & 31, wrp = tid >> 5;
    const int o0t = lane * 8, n0t = wrp * 8;
    const int kw = tid >> 6, ow = (tid & 63) * 4;   // W-tile load coords
    const int kx = tid >> 4, nx = (tid & 15) * 4;   // X-tile load coords

    ull acc[8][4];
#pragma unroll
    for (int oi = 0; oi < 8; oi++)
#pragma unroll
        for (int nj = 0; nj < 4; nj++) acc[oi][nj] = 0ull;

    // prologue: tile 0
#pragma unroll
    for (int r = 0; r < 4; r++)
        cp16(&s_w[0][(kw + 4*r) * 256 + ow], &g_WqT[(kw + 4*r) * 256 + ow]);
    cp16(&s_x[0][kx * 64 + nx], &x[(size_t)(b * 256 + kx) * 4096 + n0 + nx]);
    CP_COMMIT(); CP_WAIT0();
    __syncthreads();

    for (int it = 0; it < 16; it++) {
        const int cur = it & 1;
        if (it < 15) {
            const int c0 = (it + 1) * 16, nb = cur ^ 1;
#pragma unroll
            for (int r = 0; r < 4; r++)
                cp16(&s_w[nb][(kw + 4*r) * 256 + ow], &g_WqT[(c0 + kw + 4*r) * 256 + ow]);
            cp16(&s_x[nb][kx * 64 + nx], &x[(size_t)(b * 256 + c0 + kx) * 4096 + n0 + nx]);
            CP_COMMIT();
        }
#pragma unroll
        for (int k = 0; k < 16; k++) {
            const float* wr = &s_w[cur][k * 256 + o0t];
            float4 wa = *(const float4*)wr;
            float4 wb = *(const float4*)(wr + 4);
            ull wp[8] = {pack2(wa.x, wa.x), pack2(wa.y, wa.y), pack2(wa.z, wa.z), pack2(wa.w, wa.w),
                         pack2(wb.x, wb.x), pack2(wb.y, wb.y), pack2(wb.z, wb.z), pack2(wb.w, wb.w)};
            ulonglong2 xa = *(const ulonglong2*)&s_x[cur][k * 64 + n0t];
            ulonglong2 xb = *(const ulonglong2*)&s_x[cur][k * 64 + n0t + 4];
            ull xp[4] = {xa.x, xa.y, xb.x, xb.y};
#pragma unroll
            for (int oi = 0; oi < 8; oi++)
#pragma unroll
                for (int nj = 0; nj < 4; nj++)
                    ffma2(acc[oi][nj], wp[oi], xp[nj]);
        }
        if (it < 15) CP_WAIT0();
        __syncthreads();
    }

    // unpack
    float a[8][8];
#pragma unroll
    for (int oi = 0; oi < 8; oi++)
#pragma unroll
        for (int nj = 0; nj < 4; nj++) {
            float2 v = unpack2(acc[oi][nj]);
            a[oi][2 * nj] = v.x; a[oi][2 * nj + 1] = v.y;
        }

    float4 g0 = *(const float4*)&gq[o0t], g1 = *(const float4*)&gq[o0t + 4];
    float4 b0 = *(const float4*)&bq[o0t], b1 = *(const float4*)&bq[o0t + 4];
    float gs[8] = {g0.x*0.125f, g0.y*0.125f, g0.z*0.125f, g0.w*0.125f,
                   g1.x*0.125f, g1.y*0.125f, g1.z*0.125f, g1.w*0.125f};
    float bs[8] = {b0.x*0.125f, b0.y*0.125f, b0.z*0.125f, b0.w*0.125f,
                   b1.x*0.125f, b1.y*0.125f, b1.z*0.125f, b1.w*0.125f};
    const int bn = b * 4096;
#pragma unroll
    for (int ni = 0; ni < 8; ni++) {
        float s = 0.f, q = 0.f;
#pragma unroll
        for (int oi = 0; oi < 8; oi++) { float v = a[oi][ni]; s += v; q += v * v; }
#pragma unroll
        for (int o = 16; o; o >>= 1) {
            s += __shfl_xor_sync(0xffffffffu, s, o);
            q += __shfl_xor_sync(0xffffffffu, q, o);
        }
        float mu = s * (1.f / 256.f);
        float rs = rsqrtf(q * (1.f / 256.f) - mu * mu + 1e-6f);
        float4 v0, v1;
        v0.x = (a[0][ni]-mu)*rs*gs[0]+bs[0]; v0.y = (a[1][ni]-mu)*rs*gs[1]+bs[1];
        v0.z = (a[2][ni]-mu)*rs*gs[2]+bs[2]; v0.w = (a[3][ni]-mu)*rs*gs[3]+bs[3];
        v1.x = (a[4][ni]-mu)*rs*gs[4]+bs[4]; v1.y = (a[5][ni]-mu)*rs*gs[5]+bs[5];
        v1.z = (a[6][ni]-mu)*rs*gs[6]+bs[6]; v1.w = (a[7][ni]-mu)*rs*gs[7]+bs[7];
        float* dst = &g_qT[(size_t)(bn + n0 + n0t + ni) * 256 + o0t];
        *(float4*)dst = v0; *(float4*)(dst + 4) = v1;
    }
}

// ---------------- K4: kf = LN(Wk @ kctx), per (b, l) ----------------
__global__ void __launch_bounds__(256) k_kfln(const float* __restrict__ gk,
                                              const float* __restrict__ bk) {
    __shared__ float kin[256];
    __shared__ float red[16];
    __shared__ float mu_s, rs_s;
    const int l = blockIdx.x, b = blockIdx.y, tid = threadIdx.x;
    kin[tid] = g_kctx[(b * 256 + tid) * 49 + l];
    __syncthreads();
    float acc = 0.f;
    for (int c = 0; c < 256; c++) acc += kin[c] * g_WkT[c * 256 + tid];
    float sum = acc, sq = acc * acc;
#pragma unroll
    for (int o = 16; o; o >>= 1) {
        sum += __shfl_xor_sync(0xffffffffu, sum, o);
        sq  += __shfl_xor_sync(0xffffffffu, sq,  o);
    }
    if ((tid & 31) == 0) { red[tid >> 5] = sum; red[8 + (tid >> 5)] = sq; }
    __syncthreads();
    if (tid == 0) {
        float S = 0.f, Q = 0.f;
#pragma unroll
        for (int w = 0; w < 8; w++) { S += red[w]; Q += red[8 + w]; }
        float mu = S * (1.f / 256.f);
        mu_s = mu;
        rs_s = rsqrtf(Q * (1.f / 256.f) - mu * mu + 1e-6f);
    }
    __syncthreads();
    g_kf[(b * 256 + tid) * 49 + l] = (acc - mu_s) * rs_s * gk[tid] + bk[tid];
}

// ---------------- K5: kp[b,g,m,c] = sum_l Wproj[m,l] * kf[b,g*64+c,l] --------
__global__ void __launch_bounds__(256) k_kp(const float* __restrict__ Wproj) {
    int idx = blockIdx.x * 256 + threadIdx.x;
    int c = idx & 63;
    int rest = idx >> 6;
    int m = rest % 74;
    int bg = rest / 74;
    int ch = (bg & 3) * 64 + c;
    int b = bg >> 2;
    const float* kfrow = g_kf + (b * 256 + ch) * 49;
    const float* wrow = Wproj + m * 49;
    float s = 0.f;
#pragma unroll
    for (int l = 0; l < 49; l++) s += wrow[l] * kfrow[l];
    g_kp[idx] = s;
}

// ---------------- K6: logits + rpb + softmax + AV, per (b, g, row) ----------
template <int K>
__global__ void __launch_bounds__(256) k_attn(const float* __restrict__ rpb) {
    constexpr int MK = K * K;
    constexpr int RS = 2 * K - 1;
    constexpr int M0 = (K == 5) ? 0 : 25;
    const int g = blockIdx.y + ((K == 5) ? 0 : 2);
    const int b = blockIdx.z;
    const int i = blockIdx.x;
    const int tid = threadIdx.x;

    __shared__ __align__(16) float uni[7488];
    __shared__ float lg[64 * 50];
    __shared__ float rpbs[RS * RS];
    float* qs = uni;
    float* kps = uni + 64 * 68;
    const int bn = b * 4096;

    for (int idx = tid; idx < 64 * 16; idx += 256) {
        int j = idx >> 4, cc = idx & 15;
        *(float4*)&qs[j * 68 + cc * 4] =
            *(const float4*)&g_qT[(size_t)(bn + i * 64 + j) * 256 + g * 64 + cc * 4];
    }
    const float* kpbase = g_kp + ((b * 4 + g) * 74 + M0) * 64;
    for (int idx = tid; idx < MK * 16; idx += 256)
        *(float4*)&kps[idx * 4] = *(const float4*)&kpbase[idx * 4];
    for (int idx = tid; idx < RS * RS; idx += 256)
        rpbs[idx] = rpb[(g & 1) * RS * RS + idx];
    __syncthreads();

    // logits via f32x2
    {
        int j = tid & 63, mslot = tid >> 6;
        ull qp[32];
#pragma unroll
        for (int cc = 0; cc < 16; cc++) {
            ulonglong2 t = *(const ulonglong2*)&qs[j * 68 + cc * 4];
            qp[2 * cc] = t.x; qp[2 * cc + 1] = t.y;
        }
        for (int m = mslot; m < MK; m += 4) {
            ull a0 = 0ull, a1 = 0ull;
#pragma unroll
            for (int cc = 0; cc < 16; cc++) {
                ulonglong2 kv = *(const ulonglong2*)&kps[m * 64 + cc * 4];
                ffma2(a0, qp[2 * cc], kv.x);
                ffma2(a1, qp[2 * cc + 1], kv.y);
            }
            float2 fa = unpack2(a0), fb = unpack2(a1);
            lg[j * 50 + m] = (fa.x + fa.y) + (fb.x + fb.y);
        }
    }
    __syncthreads();

    const int si = min(max(i - K / 2, 0), 64 - K);
    const int j2 = tid >> 2, sub = tid & 3;
    const int sj = min(max(j2 - K / 2, 0), 64 - K);
    {
        int ro = (K - 1) - (i - si);
        int co = (K - 1) - (j2 - sj);
        float mx = -1e30f;
        for (int m = sub; m < MK; m += 4) {
            int p = m / K, q = m - p * K;
            float v = lg[j2 * 50 + m] + rpbs[(ro + p) * RS + (co + q)];
            lg[j2 * 50 + m] = v;
            mx = fmaxf(mx, v);
        }
        mx = fmaxf(mx, __shfl_xor_sync(0xffffffffu, mx, 1));
        mx = fmaxf(mx, __shfl_xor_sync(0xffffffffu, mx, 2));
        float s = 0.f;
        for (int m = sub; m < MK; m += 4) {
            float e = __expf(lg[j2 * 50 + m] - mx);
            lg[j2 * 50 + m] = e;
            s += e;
        }
        s += __shfl_xor_sync(0xffffffffu, s, 1);
        s += __shfl_xor_sync(0xffffffffu, s, 2);
        float inv = 1.f / s;
        for (int m = sub; m < MK; m += 4) lg[j2 * 50 + m] *= inv;
    }

    // AV via f32x2, channel quarters
    float4* vs4 = (float4*)uni;
    for (int cq = 0; cq < 4; cq++) {
        __syncthreads();
        for (int idx = tid; idx < K * 64 * 4; idx += 256) {
            int p = idx >> 8, col = (idx >> 2) & 63, c4 = idx & 3;
            vs4[idx] = *(const float4*)&g_xT[(size_t)(bn + (si + p) * 64 + col) * 256 +
                                             g * 64 + cq * 16 + c4 * 4];
        }
        __syncthreads();
        ull a0 = 0ull, a1 = 0ull;
#pragma unroll
        for (int p = 0; p < K; p++)
#pragma unroll
            for (int q = 0; q < K; q++) {
                float aw = lg[j2 * 50 + p * K + q];
                ull ap = pack2(aw, aw);
                ulonglong2 v2 = *(const ulonglong2*)&vs4[(p * 64 + sj + q) * 4 + sub];
                ffma2(a0, ap, v2.x);
                ffma2(a1, ap, v2.y);
            }
        float2 r0 = unpack2(a0), r1 = unpack2(a1);
        float4 outv = make_float4(r0.x, r0.y, r1.x, r1.y);
        *(float4*)&g_avT[(size_t)(bn + i * 64 + j2) * 256 + g * 64 + cq * 16 + sub * 4] = outv;
    }
}

// ======== K7: out = BN(Wdy @ av) — f32x2 GEMM 256o x 64n, cp.async W ==========
__global__ void __launch_bounds__(256) k_out(float* __restrict__ out,
                                             const float* __restrict__ bn_g,
                                             const float* __restrict__ bn_b) {
    __shared__ __align__(16) float s_w[2][16 * 256];
    __shared__ __align__(16) float s_x[2][16 * 64];
    const int b = blockIdx.y, n0 = blockIdx.x * 64, tid = threadIdx.x;
    const int lane = tid & 31, wrp = tid >> 5;
    const int o0t = lane * 8, n0t = wrp * 8;
    const int kw = tid >> 6, ow = (tid & 63) * 4;
    const int nX = tid >> 2, cX = (tid & 3) * 4;
    const int bn = b * 4096;

    ull acc[8][4];
#pragma unroll
    for (int oi = 0; oi < 8; oi++)
#pragma unroll
        for (int nj = 0; nj < 4; nj++) acc[oi][nj] = 0ull;

    // prologue
    float4 xr = *(const float4*)&g_avT[(size_t)(bn + n0 + nX) * 256 + cX];
#pragma unroll
    for (int r = 0; r < 4; r++)
        cp16(&s_w[0][(kw + 4*r) * 256 + ow], &g_WdyT[(kw + 4*r) * 256 + ow]);
    CP_COMMIT();
    s_x[0][(cX + 0) * 64 + nX] = xr.x;
    s_x[0][(cX + 1) * 64 + nX] = xr.y;
    s_x[0][(cX + 2) * 64 + nX] = xr.z;
    s_x[0][(cX + 3) * 64 + nX] = xr.w;
    CP_WAIT0();
    __syncthreads();

    for (int it = 0; it < 16; it++) {
        const int cur = it & 1;
        if (it < 15) {
            const int c0 = (it + 1) * 16, nb = cur ^ 1;
            xr = *(const float4*)&g_avT[(size_t)(bn + n0 + nX) * 256 + c0 + cX];
#pragma unroll
            for (int r = 0; r < 4; r++)
                cp16(&s_w[nb][(kw + 4*r) * 256 + ow], &g_WdyT[(c0 + kw + 4*r) * 256 + ow]);
            CP_COMMIT();
        }
#pragma unroll
        for (int k = 0; k < 16; k++) {
            const float* wr = &s_w[cur][k * 256 + o0t];
            float4 wa = *(const float4*)wr;
            float4 wb = *(const float4*)(wr + 4);
            ull wp[8] = {pack2(wa.x, wa.x), pack2(wa.y, wa.y), pack2(wa.z, wa.z), pack2(wa.w, wa.w),
                         pack2(wb.x, wb.x), pack2(wb.y, wb.y), pack2(wb.z, wb.z), pack2(wb.w, wb.w)};
            ulonglong2 xa = *(const ulonglong2*)&s_x[cur][k * 64 + n0t];
            ulonglong2 xb = *(const ulonglong2*)&s_x[cur][k * 64 + n0t + 4];
            ull xp[4] = {xa.x, xa.y, xb.x, xb.y};
#pragma unroll
            for (int oi = 0; oi < 8; oi++)
#pragma unroll
                for (int nj = 0; nj < 4; nj++)
                    ffma2(acc[oi][nj], wp[oi], xp[nj]);
        }
        if (it < 15) {
            const int nb = cur ^ 1;
            s_x[nb][(cX + 0) * 64 + nX] = xr.x;
            s_x[nb][(cX + 1) * 64 + nX] = xr.y;
            s_x[nb][(cX + 2) * 64 + nX] = xr.z;
            s_x[nb][(cX + 3) * 64 + nX] = xr.w;
            CP_WAIT0();
        }
        __syncthreads();
    }

    const float rinv = rsqrtf(1.f + 1e-5f);
    float4 g0 = *(const float4*)&bn_g[o0t], g1 = *(const float4*)&bn_g[o0t + 4];
    float4 b0 = *(const float4*)&bn_b[o0t], b1 = *(const float4*)&bn_b[o0t + 4];
    float gs[8] = {g0.x*rinv, g0.y*rinv, g0.z*rinv, g0.w*rinv,
                   g1.x*rinv, g1.y*rinv, g1.z*rinv, g1.w*rinv};
    float bs[8] = {b0.x, b0.y, b0.z, b0.w, b1.x, b1.y, b1.z, b1.w};
#pragma unroll
    for (int oi = 0; oi < 8; oi++) {
        float2 p0 = unpack2(acc[oi][0]), p1 = unpack2(acc[oi][1]);
        float2 p2 = unpack2(acc[oi][2]), p3 = unpack2(acc[oi][3]);
        float4 v0, v1;
        v0.x = p0.x * gs[oi] + bs[oi]; v0.y = p0.y * gs[oi] + bs[oi];
        v0.z = p1.x * gs[oi] + bs[oi]; v0.w = p1.y * gs[oi] + bs[oi];
        v1.x = p2.x * gs[oi] + bs[oi]; v1.y = p2.y * gs[oi] + bs[oi];
        v1.z = p3.x * gs[oi] + bs[oi]; v1.w = p3.y * gs[oi] + bs[oi];
        float* dst = out + (size_t)(b * 256 + o0t + oi) * 4096 + n0 + n0t;
        *(float4*)dst = v0;
        *(float4*)(dst + 4) = v1;
    }
}

// ---------------- launch ----------------
extern "C" void kernel_launch(void* const* d_in, const int* in_sizes, int n_in,
                              void* d_out, int out_size) {
    const float* x     = (const float*)d_in[0];
    const float* ctx   = (const float*)d_in[1];
    const float* Wq    = (const float*)d_in[2];
    const float* gq    = (const float*)d_in[3];
    const float* bq    = (const float*)d_in[4];
    const float* Wk    = (const float*)d_in[5];
    const float* gk    = (const float*)d_in[6];
    const float* bk    = (const float*)d_in[7];
    const float* Wproj = (const float*)d_in[8];
    const float* rpb1  = (const float*)d_in[9];
    const float* rpb2  = (const float*)d_in[10];
    const float* Wdy   = (const float*)d_in[11];
    const float* bn_g  = (const float*)d_in[12];
    const float* bn_b  = (const float*)d_in[13];
    float* out = (float*)d_out;

    dim3 b32(32, 8);
    k0_wt  <<<dim3(8, 8, 3),   b32>>>(Wq, Wk, Wdy);
    k1_xt  <<<dim3(128, 8, 4), b32>>>(x);
    k2_pool<<<196, 256>>>(ctx);
    k_qln  <<<dim3(64, 4), 256>>>(x, gq, bq);
    k_kfln <<<dim3(49, 4),  256>>>(gk, bk);
    k_kp   <<<296, 256>>>(Wproj);
    k_attn<5><<<dim3(64, 2, 4), 256>>>(rpb1);
    k_attn<7><<<dim3(64, 2, 4), 256>>>(rpb2);
    k_out  <<<dim3(64, 4), 256>>>(out, bn_g, bn_b);
}

// round 9
// speedup vs baseline: 2.0247x; 1.0200x over previous
#include <cuda_runtime.h>
#include <cuda_bf16.h>
#include <cstdint>

#define BATCH 4
#define CDIM  256
#define NPIX  4096

typedef unsigned long long ull;

// ---------------- device-global scratch (no allocation allowed) ----------------
__device__ float g_WkT [CDIM*CDIM];
__device__ float g_xT  [BATCH*NPIX*CDIM];        // x pixel-major fp32 (attn V)
__device__ float g_qT  [BATCH*NPIX*CDIM];        // q pixel-major fp32
__device__ float g_kctx[BATCH*CDIM*49];
__device__ float g_kf  [BATCH*CDIM*49];
__device__ float g_kp  [BATCH*4*74*64];
__device__ __nv_bfloat16 g_xp [BATCH*NPIX*512];  // [px][ xh(256) | xl(256) ]
__device__ __nv_bfloat16 g_avp[BATCH*NPIX*512];  // [px][ ah(256) | al(256) ]
__device__ __nv_bfloat16 g_wqp[256*512];         // [o][ wh(256) | wl(256) ]
__device__ __nv_bfloat16 g_wdp[256*512];

// ---------------- f32x2 helpers (attention) ----------------
__device__ __forceinline__ void ffma2(ull& d, ull a, ull b) {
    asm("fma.rn.f32x2 %0, %1, %2, %0;" : "+l"(d) : "l"(a), "l"(b));
}
__device__ __forceinline__ ull pack2(float lo, float hi) {
    ull r; asm("mov.b64 %0, {%1, %2};" : "=l"(r) : "f"(lo), "f"(hi)); return r;
}
__device__ __forceinline__ float2 unpack2(ull v) {
    float2 r; asm("mov.b64 {%0, %1}, %2;" : "=f"(r.x), "=f"(r.y) : "l"(v)); return r;
}

// ---------------- K0: transpose Wk only ----------------
__global__ void __launch_bounds__(256) k0_wt(const float* __restrict__ Wk) {
    __shared__ float t[32][33];
    int o0 = blockIdx.y * 32, c0 = blockIdx.x * 32;
    int tx = threadIdx.x, ty = threadIdx.y;
#pragma unroll
    for (int r = 0; r < 4; r++)
        t[ty + 8*r][tx] = Wk[(o0 + ty + 8*r) * 256 + c0 + tx];
    __syncthreads();
#pragma unroll
    for (int r = 0; r < 4; r++)
        g_WkT[(c0 + ty + 8*r) * 256 + o0 + tx] = t[tx][ty + 8*r];
}

// ---------------- K1: x -> g_xT (fp32) + g_xp (bf16 hi/lo) ----------------
__global__ void __launch_bounds__(256) k1_xt(const float* __restrict__ x) {
    __shared__ float t[32][33];
    int b = blockIdx.z, n0 = blockIdx.x * 32, c0 = blockIdx.y * 32;
    int tx = threadIdx.x, ty = threadIdx.y;
#pragma unroll
    for (int r = 0; r < 4; r++)
        t[ty + 8*r][tx] = x[(size_t)(b * 256 + c0 + ty + 8*r) * 4096 + n0 + tx];
    __syncthreads();
#pragma unroll
    for (int r = 0; r < 4; r++) {
        int row = b * 4096 + n0 + ty + 8*r, col = c0 + tx;
        float v = t[tx][ty + 8*r];
        g_xT[(size_t)row * 256 + col] = v;
        __nv_bfloat16 h = __float2bfloat16(v);
        g_xp[(size_t)row * 512 + col] = h;
        g_xp[(size_t)row * 512 + 256 + col] = __float2bfloat16(v - __bfloat162float(h));
    }
}

// ---------------- K2: ctx 8x8 mean pool ----------------
__global__ void __launch_bounds__(256) k2_pool(const float* __restrict__ ctx) {
    int idx = blockIdx.x * 256 + threadIdx.x;
    int l = idx % 49;
    int c = (idx / 49) & 255;
    int b = idx / (49 * 256);
    int i = l / 7, j = l % 7;
    const float* base = ctx + ((size_t)(b * 256 + c) * 56 + i * 8) * 56 + j * 8;
    float s = 0.f;
#pragma unroll
    for (int p = 0; p < 8; p++)
#pragma unroll
        for (int q = 0; q < 8; q++)
            s += base[p * 56 + q];
    g_kctx[idx] = s * (1.f / 64.f);
}

// ---------------- K-wexp: Wq/Wdy -> bf16 hi/lo ([o][ hi | lo ]) ----------------
__global__ void __launch_bounds__(256) k_wexp(const float* __restrict__ Wq,
                                              const float* __restrict__ Wdy) {
    int idx = blockIdx.x * 256 + threadIdx.x;          // 32768 total
    int sel = idx >> 14;
    int i2 = idx & 16383;
    int o = i2 >> 6, c = (i2 & 63) * 4;
    const float* W = sel ? Wdy : Wq;
    __nv_bfloat16* D = sel ? g_wdp : g_wqp;
    float4 v = *(const float4*)&W[o * 256 + c];
    __nv_bfloat16 h0 = __float2bfloat16(v.x), h1 = __float2bfloat16(v.y);
    __nv_bfloat16 h2 = __float2bfloat16(v.z), h3 = __float2bfloat16(v.w);
    __nv_bfloat162 a, bb;
    a.x = h0; a.y = h1; bb.x = h2; bb.y = h3;
    *(__nv_bfloat162*)&D[o * 512 + c] = a;
    *(__nv_bfloat162*)&D[o * 512 + c + 2] = bb;
    __nv_bfloat162 la, lb;
    la.x = __float2bfloat16(v.x - __bfloat162float(h0));
    la.y = __float2bfloat16(v.y - __bfloat162float(h1));
    lb.x = __float2bfloat16(v.z - __bfloat162float(h2));
    lb.y = __float2bfloat16(v.w - __bfloat162float(h3));
    *(__nv_bfloat162*)&D[o * 512 + 256 + c] = la;
    *(__nv_bfloat162*)&D[o * 512 + 256 + c + 2] = lb;
}

// ======== mma.sync split-bf16 GEMM: D[128 px, 256 o] = A @ B^T, K'=768 ========
// MODE 0: fused LN*SCALE -> g_qT (px-major). MODE 1: fused BN -> outp (ch-major).
template <int MODE>
__global__ void __launch_bounds__(256) k_gemm(const float* __restrict__ s0,
                                              const float* __restrict__ s1,
                                              float* __restrict__ outp) {
    __shared__ __align__(16) unsigned char sm[36864];
    __nv_bfloat16* As = (__nv_bfloat16*)sm;            // [128][40] bf16
    __nv_bfloat16* Bs = (__nv_bfloat16*)(sm + 10240);  // [256][40] bf16
    float* redS = (float*)(sm + 30720);                // [4][128]
    float* redQ = (float*)(sm + 32768);                // [4][128]
    float* gb   = (float*)(sm + 34816);                // [512]

    const int tid = threadIdx.x, wid = tid >> 5, lane = tid & 31;
    const int wm = wid >> 2, wn = wid & 3;
    const int g = lane >> 2, l = lane & 3;
    const int mbase = blockIdx.x * 128;
    const __nv_bfloat16* Ag = (MODE == 0) ? g_xp : g_avp;
    const __nv_bfloat16* Bg = (MODE == 0) ? g_wqp : g_wdp;

    gb[tid] = s0[tid];
    gb[256 + tid] = s1[tid];

    float c[4][8][4];
#pragma unroll
    for (int mt = 0; mt < 4; mt++)
#pragma unroll
        for (int nt = 0; nt < 8; nt++)
#pragma unroll
            for (int q = 0; q < 4; q++) c[mt][nt][q] = 0.f;

    float4 pa[2], pb[4];
    const int pA = (tid * 2) >> 2, jA = (tid * 2) & 3;       // r=0; r=1 -> jA+1 pattern
    const int oB = tid, /* tid*4>>2 */ dummy = 0; (void)dummy;

    // prologue loads (product 0 = hh, kc = 0)
#pragma unroll
    for (int r = 0; r < 2; r++) {
        int s = tid * 2 + r, p = s >> 2, j = s & 3;
        pa[r] = *(const float4*)&Ag[(size_t)(mbase + p) * 512 + 0 + 0 + j * 8];
    }
#pragma unroll
    for (int r = 0; r < 4; r++) {
        int s = tid * 4 + r, o = s >> 2, j = s & 3;
        pb[r] = *(const float4*)&Bg[(size_t)o * 512 + 0 + 0 + j * 8];
    }

    for (int it = 0; it < 24; it++) {
        // store staged tile
#pragma unroll
        for (int r = 0; r < 2; r++) {
            int s = tid * 2 + r, p = s >> 2, j = s & 3;
            *(float4*)((char*)As + p * 80 + j * 16) = pa[r];
        }
#pragma unroll
        for (int r = 0; r < 4; r++) {
            int s = tid * 4 + r, o = s >> 2, j = s & 3;
            *(float4*)((char*)Bs + o * 80 + j * 16) = pb[r];
        }
        __syncthreads();
        if (it < 23) {
            int nx = it + 1, pr = nx >> 3, kc = (nx & 7) * 32;
            int selA = (pr == 2) ? 256 : 0;      // products: hh, hl, lh
            int selB = (pr == 1) ? 256 : 0;
#pragma unroll
            for (int r = 0; r < 2; r++) {
                int s = tid * 2 + r, p = s >> 2, j = s & 3;
                pa[r] = *(const float4*)&Ag[(size_t)(mbase + p) * 512 + selA + kc + j * 8];
            }
#pragma unroll
            for (int r = 0; r < 4; r++) {
                int s = tid * 4 + r, o = s >> 2, j = s & 3;
                pb[r] = *(const float4*)&Bg[(size_t)o * 512 + selB + kc + j * 8];
            }
        }
        // compute: 2 k16-steps x (4 m-tiles x 8 n-tiles)
#pragma unroll
        for (int s = 0; s < 2; s++) {
            uint32_t af[4][4];
#pragma unroll
            for (int mt = 0; mt < 4; mt++) {
                const char* base = (char*)As + (wm * 64 + mt * 16 + g) * 80 + s * 32 + 4 * l;
                af[mt][0] = *(const uint32_t*)base;
                af[mt][1] = *(const uint32_t*)(base + 8 * 80);
                af[mt][2] = *(const uint32_t*)(base + 16);
                af[mt][3] = *(const uint32_t*)(base + 8 * 80 + 16);
            }
#pragma unroll
            for (int nt = 0; nt < 8; nt++) {
                const char* bbp = (char*)Bs + (wn * 64 + nt * 8 + g) * 80 + s * 32 + 4 * l;
                uint32_t b0 = *(const uint32_t*)bbp;
                uint32_t b1 = *(const uint32_t*)(bbp + 16);
#pragma unroll
                for (int mt = 0; mt < 4; mt++)
                    asm("mma.sync.aligned.m16n8k16.row.col.f32.bf16.bf16.f32 "
                        "{%0,%1,%2,%3}, {%4,%5,%6,%7}, {%8,%9}, {%0,%1,%2,%3};"
                        : "+f"(c[mt][nt][0]), "+f"(c[mt][nt][1]),
                          "+f"(c[mt][nt][2]), "+f"(c[mt][nt][3])
                        : "r"(af[mt][0]), "r"(af[mt][1]), "r"(af[mt][2]), "r"(af[mt][3]),
                          "r"(b0), "r"(b1));
            }
        }
        __syncthreads();
    }

    if (MODE == 0) {
        // LN per pixel: quad shfl + cross-warp smem reduce
#pragma unroll
        for (int mt = 0; mt < 4; mt++)
#pragma unroll
            for (int h = 0; h < 2; h++) {
                float su = 0.f, sq = 0.f;
#pragma unroll
                for (int nt = 0; nt < 8; nt++) {
                    float v0 = c[mt][nt][2 * h], v1 = c[mt][nt][2 * h + 1];
                    su += v0 + v1; sq += v0 * v0 + v1 * v1;
                }
                su += __shfl_xor_sync(0xffffffffu, su, 1);
                sq += __shfl_xor_sync(0xffffffffu, sq, 1);
                su += __shfl_xor_sync(0xffffffffu, su, 2);
                sq += __shfl_xor_sync(0xffffffffu, sq, 2);
                int px = wm * 64 + mt * 16 + g + 8 * h;
                if (l == 0) { redS[wn * 128 + px] = su; redQ[wn * 128 + px] = sq; }
            }
        __syncthreads();
#pragma unroll
        for (int mt = 0; mt < 4; mt++)
#pragma unroll
            for (int h = 0; h < 2; h++) {
                int px = wm * 64 + mt * 16 + g + 8 * h;
                float su = redS[px] + redS[128 + px] + redS[256 + px] + redS[384 + px];
                float sq = redQ[px] + redQ[128 + px] + redQ[256 + px] + redQ[384 + px];
                float mu = su * (1.f / 256.f);
                float rs = rsqrtf(sq * (1.f / 256.f) - mu * mu + 1e-6f);
                float* dst = &g_qT[(size_t)(mbase + px) * 256];
#pragma unroll
                for (int nt = 0; nt < 8; nt++) {
                    int ch = wn * 64 + nt * 8 + 2 * l;
                    float2 o2;
                    o2.x = (c[mt][nt][2*h]   - mu) * rs * gb[ch]   * 0.125f + gb[256+ch]   * 0.125f;
                    o2.y = (c[mt][nt][2*h+1] - mu) * rs * gb[ch+1] * 0.125f + gb[256+ch+1] * 0.125f;
                    *(float2*)&dst[ch] = o2;
                }
            }
    } else {
        // BN + channel-major store via smem transpose, 64-ch slabs
        const float rinv = rsqrtf(1.f + 1e-5f);
        const int b = mbase >> 12, n0 = mbase & 4095;
        float* stage = (float*)sm;   // [64][132]
        for (int sl = 0; sl < 4; sl++) {
            __syncthreads();
            if (wn == sl) {
#pragma unroll
                for (int nt = 0; nt < 8; nt++) {
                    int cl = nt * 8 + 2 * l;
                    float gs0 = gb[sl*64 + cl] * rinv,     bs0 = gb[256 + sl*64 + cl];
                    float gs1 = gb[sl*64 + cl + 1] * rinv, bs1 = gb[256 + sl*64 + cl + 1];
#pragma unroll
                    for (int mt = 0; mt < 4; mt++) {
                        int px = wm * 64 + mt * 16 + g;
                        stage[cl * 132 + px]           = c[mt][nt][0] * gs0 + bs0;
                        stage[(cl + 1) * 132 + px]     = c[mt][nt][1] * gs1 + bs1;
                        stage[cl * 132 + px + 8]       = c[mt][nt][2] * gs0 + bs0;
                        stage[(cl + 1) * 132 + px + 8] = c[mt][nt][3] * gs1 + bs1;
                    }
                }
            }
            __syncthreads();
            int row = tid >> 2, seg = (tid & 3) * 32;
            float* dst = outp + (size_t)(b * 256 + sl * 64 + row) * 4096 + n0 + seg;
            const float* src = &stage[row * 132 + seg];
#pragma unroll
            for (int q = 0; q < 8; q++)
                *(float4*)&dst[q * 4] = *(const float4*)&src[q * 4];
        }
    }
}

// ---------------- K4: kf = LN(Wk @ kctx), per (b, l) ----------------
__global__ void __launch_bounds__(256) k_kfln(const float* __restrict__ gk,
                                              const float* __restrict__ bk) {
    __shared__ float kin[256];
    __shared__ float red[16];
    __shared__ float mu_s, rs_s;
    const int l = blockIdx.x, b = blockIdx.y, tid = threadIdx.x;
    kin[tid] = g_kctx[(b * 256 + tid) * 49 + l];
    __syncthreads();
    float acc = 0.f;
    for (int c = 0; c < 256; c++) acc += kin[c] * g_WkT[c * 256 + tid];
    float sum = acc, sq = acc * acc;
#pragma unroll
    for (int o = 16; o; o >>= 1) {
        sum += __shfl_xor_sync(0xffffffffu, sum, o);
        sq  += __shfl_xor_sync(0xffffffffu, sq,  o);
    }
    if ((tid & 31) == 0) { red[tid >> 5] = sum; red[8 + (tid >> 5)] = sq; }
    __syncthreads();
    if (tid == 0) {
        float S = 0.f, Q = 0.f;
#pragma unroll
        for (int w = 0; w < 8; w++) { S += red[w]; Q += red[8 + w]; }
        float mu = S * (1.f / 256.f);
        mu_s = mu;
        rs_s = rsqrtf(Q * (1.f / 256.f) - mu * mu + 1e-6f);
    }
    __syncthreads();
    g_kf[(b * 256 + tid) * 49 + l] = (acc - mu_s) * rs_s * gk[tid] + bk[tid];
}

// ---------------- K5: kp ----------------
__global__ void __launch_bounds__(256) k_kp(const float* __restrict__ Wproj) {
    int idx = blockIdx.x * 256 + threadIdx.x;
    int c = idx & 63;
    int rest = idx >> 6;
    int m = rest % 74;
    int bg = rest / 74;
    int ch = (bg & 3) * 64 + c;
    int b = bg >> 2;
    const float* kfrow = g_kf + (b * 256 + ch) * 49;
    const float* wrow = Wproj + m * 49;
    float s = 0.f;
#pragma unroll
    for (int l = 0; l < 49; l++) s += wrow[l] * kfrow[l];
    g_kp[idx] = s;
}

// ---------------- K6: logits + rpb + softmax + AV ----------------
template <int K>
__global__ void __launch_bounds__(256) k_attn(const float* __restrict__ rpb) {
    constexpr int MK = K * K;
    constexpr int RS = 2 * K - 1;
    constexpr int M0 = (K == 5) ? 0 : 25;
    const int g = blockIdx.y + ((K == 5) ? 0 : 2);
    const int b = blockIdx.z;
    const int i = blockIdx.x;
    const int tid = threadIdx.x;

    __shared__ __align__(16) float uni[7488];
    __shared__ float lg[64 * 50];
    __shared__ float rpbs[RS * RS];
    float* qs = uni;
    float* kps = uni + 64 * 68;
    const int bn = b * 4096;

    for (int idx = tid; idx < 64 * 16; idx += 256) {
        int j = idx >> 4, cc = idx & 15;
        *(float4*)&qs[j * 68 + cc * 4] =
            *(const float4*)&g_qT[(size_t)(bn + i * 64 + j) * 256 + g * 64 + cc * 4];
    }
    const float* kpbase = g_kp + ((b * 4 + g) * 74 + M0) * 64;
    for (int idx = tid; idx < MK * 16; idx += 256)
        *(float4*)&kps[idx * 4] = *(const float4*)&kpbase[idx * 4];
    for (int idx = tid; idx < RS * RS; idx += 256)
        rpbs[idx] = rpb[(g & 1) * RS * RS + idx];
    __syncthreads();

    {
        int j = tid & 63, mslot = tid >> 6;
        ull qp[32];
#pragma unroll
        for (int cc = 0; cc < 16; cc++) {
            ulonglong2 t = *(const ulonglong2*)&qs[j * 68 + cc * 4];
            qp[2 * cc] = t.x; qp[2 * cc + 1] = t.y;
        }
        for (int m = mslot; m < MK; m += 4) {
            ull a0 = 0ull, a1 = 0ull;
#pragma unroll
            for (int cc = 0; cc < 16; cc++) {
                ulonglong2 kv = *(const ulonglong2*)&kps[m * 64 + cc * 4];
                ffma2(a0, qp[2 * cc], kv.x);
                ffma2(a1, qp[2 * cc + 1], kv.y);
            }
            float2 fa = unpack2(a0), fb = unpack2(a1);
            lg[j * 50 + m] = (fa.x + fa.y) + (fb.x + fb.y);
        }
    }
    __syncthreads();

    const int si = min(max(i - K / 2, 0), 64 - K);
    const int j2 = tid >> 2, sub = tid & 3;
    const int sj = min(max(j2 - K / 2, 0), 64 - K);
    {
        int ro = (K - 1) - (i - si);
        int co = (K - 1) - (j2 - sj);
        float mx = -1e30f;
        for (int m = sub; m < MK; m += 4) {
            int p = m / K, q = m - p * K;
            float v = lg[j2 * 50 + m] + rpbs[(ro + p) * RS + (co + q)];
            lg[j2 * 50 + m] = v;
            mx = fmaxf(mx, v);
        }
        mx = fmaxf(mx, __shfl_xor_sync(0xffffffffu, mx, 1));
        mx = fmaxf(mx, __shfl_xor_sync(0xffffffffu, mx, 2));
        float s = 0.f;
        for (int m = sub; m < MK; m += 4) {
            float e = __expf(lg[j2 * 50 + m] - mx);
            lg[j2 * 50 + m] = e;
            s += e;
        }
        s += __shfl_xor_sync(0xffffffffu, s, 1);
        s += __shfl_xor_sync(0xffffffffu, s, 2);
        float inv = 1.f / s;
        for (int m = sub; m < MK; m += 4) lg[j2 * 50 + m] *= inv;
    }

    float4* vs4 = (float4*)uni;
    for (int cq = 0; cq < 4; cq++) {
        __syncthreads();
        for (int idx = tid; idx < K * 64 * 4; idx += 256) {
            int p = idx >> 8, col = (idx >> 2) & 63, c4 = idx & 3;
            vs4[idx] = *(const float4*)&g_xT[(size_t)(bn + (si + p) * 64 + col) * 256 +
                                             g * 64 + cq * 16 + c4 * 4];
        }
        __syncthreads();
        ull a0 = 0ull, a1 = 0ull;
#pragma unroll
        for (int p = 0; p < K; p++)
#pragma unroll
            for (int q = 0; q < K; q++) {
                float aw = lg[j2 * 50 + p * K + q];
                ull ap = pack2(aw, aw);
                ulonglong2 v2 = *(const ulonglong2*)&vs4[(p * 64 + sj + q) * 4 + sub];
                ffma2(a0, ap, v2.x);
                ffma2(a1, ap, v2.y);
            }
        float2 r0 = unpack2(a0), r1 = unpack2(a1);
        // write bf16 hi/lo split directly for the output GEMM
        const int oc = g * 64 + cq * 16 + sub * 4;
        const size_t px = (size_t)(bn + i * 64 + j2) * 512;
        __nv_bfloat16 h0 = __float2bfloat16(r0.x), h1 = __float2bfloat16(r0.y);
        __nv_bfloat16 h2 = __float2bfloat16(r1.x), h3 = __float2bfloat16(r1.y);
        __nv_bfloat162 ha, hb;
        ha.x = h0; ha.y = h1; hb.x = h2; hb.y = h3;
        *(__nv_bfloat162*)&g_avp[px + oc] = ha;
        *(__nv_bfloat162*)&g_avp[px + oc + 2] = hb;
        __nv_bfloat162 la, lb;
        la.x = __float2bfloat16(r0.x - __bfloat162float(h0));
        la.y = __float2bfloat16(r0.y - __bfloat162float(h1));
        lb.x = __float2bfloat16(r1.x - __bfloat162float(h2));
        lb.y = __float2bfloat16(r1.y - __bfloat162float(h3));
        *(__nv_bfloat162*)&g_avp[px + 256 + oc] = la;
        *(__nv_bfloat162*)&g_avp[px + 256 + oc + 2] = lb;
    }
}

// ---------------- launch ----------------
extern "C" void kernel_launch(void* const* d_in, const int* in_sizes, int n_in,
                              void* d_out, int out_size) {
    const float* x     = (const float*)d_in[0];
    const float* ctx   = (const float*)d_in[1];
    const float* Wq    = (const float*)d_in[2];
    const float* gq    = (const float*)d_in[3];
    const float* bq    = (const float*)d_in[4];
    const float* Wk    = (const float*)d_in[5];
    const float* gk    = (const float*)d_in[6];
    const float* bk    = (const float*)d_in[7];
    const float* Wproj = (const float*)d_in[8];
    const float* rpb1  = (const float*)d_in[9];
    const float* rpb2  = (const float*)d_in[10];
    const float* Wdy   = (const float*)d_in[11];
    const float* bn_g  = (const float*)d_in[12];
    const float* bn_b  = (const float*)d_in[13];
    float* out = (float*)d_out;

    dim3 b32(32, 8);
    k0_wt  <<<dim3(8, 8),      b32>>>(Wk);
    k1_xt  <<<dim3(128, 8, 4), b32>>>(x);
    k2_pool<<<196, 256>>>(ctx);
    k_wexp <<<128, 256>>>(Wq, Wdy);
    k_gemm<0><<<128, 256>>>(gq, bq, nullptr);
    k_kfln <<<dim3(49, 4), 256>>>(gk, bk);
    k_kp   <<<296, 256>>>(Wproj);
    k_attn<5><<<dim3(64, 2, 4), 256>>>(rpb1);
    k_attn<7><<<dim3(64, 2, 4), 256>>>(rpb2);
    k_gemm<1><<<128, 256>>>(bn_g, bn_b, out);
}

// round 11
// speedup vs baseline: 2.1102x; 1.0423x over previous
#include <cuda_runtime.h>
#include <cuda_bf16.h>
#include <cstdint>

#define BATCH 4
#define CDIM  256
#define NPIX  4096

typedef unsigned long long ull;

// ---------------- device-global scratch (no allocation allowed) ----------------
__device__ float g_WkT [CDIM*CDIM];
__device__ float g_xT  [BATCH*NPIX*CDIM];        // x pixel-major fp32 (attn V)
__device__ float g_qT  [BATCH*NPIX*CDIM];        // q pixel-major fp32
__device__ float g_kctx[BATCH*CDIM*49];
__device__ float g_kf  [BATCH*CDIM*49];
__device__ float g_kp  [BATCH*4*74*64];
__device__ __nv_bfloat16 g_xp [BATCH*NPIX*512];  // [px][ xh(256) | xl(256) ]
__device__ __nv_bfloat16 g_avp[BATCH*NPIX*512];  // [px][ ah(256) | al(256) ]
__device__ __nv_bfloat16 g_wqp[256*512];         // [o][ wh(256) | wl(256) ]
__device__ __nv_bfloat16 g_wdp[256*512];

// ---------------- helpers ----------------
__device__ __forceinline__ void ffma2(ull& d, ull a, ull b) {
    asm("fma.rn.f32x2 %0, %1, %2, %0;" : "+l"(d) : "l"(a), "l"(b));
}
__device__ __forceinline__ ull pack2(float lo, float hi) {
    ull r; asm("mov.b64 %0, {%1, %2};" : "=l"(r) : "f"(lo), "f"(hi)); return r;
}
__device__ __forceinline__ float2 unpack2(ull v) {
    float2 r; asm("mov.b64 {%0, %1}, %2;" : "=f"(r.x), "=f"(r.y) : "l"(v)); return r;
}
__device__ __forceinline__ void cp16(void* smem, const void* gmem) {
    unsigned s = (unsigned)__cvta_generic_to_shared(smem);
    asm volatile("cp.async.cg.shared.global [%0], [%1], 16;\n" :: "r"(s), "l"(gmem));
}
#define CP_COMMIT() asm volatile("cp.async.commit_group;\n" ::: "memory")
__device__ __forceinline__ void ldmx4(uint32_t* r, uint32_t addr) {
    asm volatile("ldmatrix.sync.aligned.m8n8.x4.shared.b16 {%0,%1,%2,%3}, [%4];"
        : "=r"(r[0]), "=r"(r[1]), "=r"(r[2]), "=r"(r[3]) : "r"(addr));
}

// ---------------- K0: transpose Wk only ----------------
__global__ void __launch_bounds__(256) k0_wt(const float* __restrict__ Wk) {
    __shared__ float t[32][33];
    int o0 = blockIdx.y * 32, c0 = blockIdx.x * 32;
    int tx = threadIdx.x, ty = threadIdx.y;
#pragma unroll
    for (int r = 0; r < 4; r++)
        t[ty + 8*r][tx] = Wk[(o0 + ty + 8*r) * 256 + c0 + tx];
    __syncthreads();
#pragma unroll
    for (int r = 0; r < 4; r++)
        g_WkT[(c0 + ty + 8*r) * 256 + o0 + tx] = t[tx][ty + 8*r];
}

// ---------------- K1: x -> g_xT (fp32) + g_xp (bf16 hi/lo) ----------------
__global__ void __launch_bounds__(256) k1_xt(const float* __restrict__ x) {
    __shared__ float t[32][33];
    int b = blockIdx.z, n0 = blockIdx.x * 32, c0 = blockIdx.y * 32;
    int tx = threadIdx.x, ty = threadIdx.y;
#pragma unroll
    for (int r = 0; r < 4; r++)
        t[ty + 8*r][tx] = x[(size_t)(b * 256 + c0 + ty + 8*r) * 4096 + n0 + tx];
    __syncthreads();
#pragma unroll
    for (int r = 0; r < 4; r++) {
        int row = b * 4096 + n0 + ty + 8*r, col = c0 + tx;
        float v = t[tx][ty + 8*r];
        g_xT[(size_t)row * 256 + col] = v;
        __nv_bfloat16 h = __float2bfloat16(v);
        g_xp[(size_t)row * 512 + col] = h;
        g_xp[(size_t)row * 512 + 256 + col] = __float2bfloat16(v - __bfloat162float(h));
    }
}

// ---------------- K2: ctx 8x8 mean pool ----------------
__global__ void __launch_bounds__(256) k2_pool(const float* __restrict__ ctx) {
    int idx = blockIdx.x * 256 + threadIdx.x;
    int l = idx % 49;
    int c = (idx / 49) & 255;
    int b = idx / (49 * 256);
    int i = l / 7, j = l % 7;
    const float* base = ctx + ((size_t)(b * 256 + c) * 56 + i * 8) * 56 + j * 8;
    float s = 0.f;
#pragma unroll
    for (int p = 0; p < 8; p++)
#pragma unroll
        for (int q = 0; q < 8; q++)
            s += base[p * 56 + q];
    g_kctx[idx] = s * (1.f / 64.f);
}

// ---------------- K-wexp: Wq/Wdy -> bf16 hi/lo ([o][ hi | lo ]) ----------------
__global__ void __launch_bounds__(256) k_wexp(const float* __restrict__ Wq,
                                              const float* __restrict__ Wdy) {
    int idx = blockIdx.x * 256 + threadIdx.x;          // 32768 total
    int sel = idx >> 14;
    int i2 = idx & 16383;
    int o = i2 >> 6, c = (i2 & 63) * 4;
    const float* W = sel ? Wdy : Wq;
    __nv_bfloat16* D = sel ? g_wdp : g_wqp;
    float4 v = *(const float4*)&W[o * 256 + c];
    __nv_bfloat16 h0 = __float2bfloat16(v.x), h1 = __float2bfloat16(v.y);
    __nv_bfloat16 h2 = __float2bfloat16(v.z), h3 = __float2bfloat16(v.w);
    __nv_bfloat162 a, bb;
    a.x = h0; a.y = h1; bb.x = h2; bb.y = h3;
    *(__nv_bfloat162*)&D[o * 512 + c] = a;
    *(__nv_bfloat162*)&D[o * 512 + c + 2] = bb;
    __nv_bfloat162 la, lb;
    la.x = __float2bfloat16(v.x - __bfloat162float(h0));
    la.y = __float2bfloat16(v.y - __bfloat162float(h1));
    lb.x = __float2bfloat16(v.z - __bfloat162float(h2));
    lb.y = __float2bfloat16(v.w - __bfloat162float(h3));
    *(__nv_bfloat162*)&D[o * 512 + 256 + c] = la;
    *(__nv_bfloat162*)&D[o * 512 + 256 + c + 2] = lb;
}

// ======== mma.sync split-bf16 GEMM: D[128 px, 256 o] = A @ B^T, K'=768 ========
// ldmatrix fragments + cp.async 2-stage double buffer.
// MODE 0: fused LN*SCALE -> g_qT (px-major). MODE 1: fused BN -> outp (ch-major).
#define STG 30720
template <int MODE>
__global__ void __launch_bounds__(256) k_gemm(const float* __restrict__ s0,
                                              const float* __restrict__ s1,
                                              float* __restrict__ outp) {
    extern __shared__ __align__(16) unsigned char sm[];   // 2*30720 + 2048
    float* gb = (float*)(sm + 2 * STG);                   // [512]

    const int tid = threadIdx.x, wid = tid >> 5, lane = tid & 31;
    const int wm = wid >> 2, wn = wid & 3;
    const int g = lane >> 2, l = lane & 3;
    const int mbase = blockIdx.x * 128;
    const __nv_bfloat16* Ag = (MODE == 0) ? g_xp : g_avp;
    const __nv_bfloat16* Bg = (MODE == 0) ? g_wqp : g_wdp;

    gb[tid] = s0[tid];
    gb[256 + tid] = s1[tid];

    float c[4][8][4];
#pragma unroll
    for (int mt = 0; mt < 4; mt++)
#pragma unroll
        for (int nt = 0; nt < 8; nt++)
#pragma unroll
            for (int q = 0; q < 4; q++) c[mt][nt][q] = 0.f;

    // ldmatrix per-lane base addresses
    const uint32_t smem_u32 = (uint32_t)__cvta_generic_to_shared(sm);
    const uint32_t aBase = smem_u32 +
        (uint32_t)((wm * 64 + ((lane >> 3) & 1) * 8 + (lane & 7)) * 80 + (lane >> 4) * 16);
    const uint32_t bBase = smem_u32 + 10240u +
        (uint32_t)((wn * 64 + ((lane >> 4) & 1) * 8 + (lane & 7)) * 80 + ((lane >> 3) & 1) * 16);

    // prologue: stage 0 (product hh, kc = 0)
#pragma unroll
    for (int r = 0; r < 2; r++) {
        int s2 = tid * 2 + r, p = s2 >> 2, j = s2 & 3;
        cp16(sm + p * 80 + j * 16, &Ag[(size_t)(mbase + p) * 512 + j * 8]);
    }
#pragma unroll
    for (int j = 0; j < 4; j++)
        cp16(sm + 10240 + tid * 80 + j * 16, &Bg[(size_t)tid * 512 + j * 8]);
    CP_COMMIT();

    for (int it = 0; it < 24; it++) {
        const int cur = it & 1;
        if (it < 23) {
            const int nx = it + 1, pr = nx >> 3, kc = (nx & 7) * 32;
            const int selA = (pr == 2) ? 256 : 0;      // products: hh, hl, lh
            const int selB = (pr == 1) ? 256 : 0;
            const int nb = cur ^ 1;
#pragma unroll
            for (int r = 0; r < 2; r++) {
                int s2 = tid * 2 + r, p = s2 >> 2, j = s2 & 3;
                cp16(sm + nb * STG + p * 80 + j * 16,
                     &Ag[(size_t)(mbase + p) * 512 + selA + kc + j * 8]);
            }
#pragma unroll
            for (int j = 0; j < 4; j++)
                cp16(sm + nb * STG + 10240 + tid * 80 + j * 16,
                     &Bg[(size_t)tid * 512 + selB + kc + j * 8]);
            CP_COMMIT();
            asm volatile("cp.async.wait_group 1;\n" ::: "memory");
        } else {
            asm volatile("cp.async.wait_group 0;\n" ::: "memory");
        }
        __syncthreads();
        const uint32_t stOff = (uint32_t)(cur * STG);
#pragma unroll
        for (int s = 0; s < 2; s++) {
            uint32_t af[4][4], bf[8][2];
#pragma unroll
            for (int mt = 0; mt < 4; mt++)
                ldmx4(af[mt], aBase + stOff + (uint32_t)(mt * 16 * 80 + s * 32));
#pragma unroll
            for (int p = 0; p < 4; p++) {
                uint32_t r[4];
                ldmx4(r, bBase + stOff + (uint32_t)(p * 16 * 80 + s * 32));
                bf[2*p][0] = r[0]; bf[2*p][1] = r[1];
                bf[2*p+1][0] = r[2]; bf[2*p+1][1] = r[3];
            }
#pragma unroll
            for (int nt = 0; nt < 8; nt++)
#pragma unroll
                for (int mt = 0; mt < 4; mt++)
                    asm("mma.sync.aligned.m16n8k16.row.col.f32.bf16.bf16.f32 "
                        "{%0,%1,%2,%3}, {%4,%5,%6,%7}, {%8,%9}, {%0,%1,%2,%3};"
                        : "+f"(c[mt][nt][0]), "+f"(c[mt][nt][1]),
                          "+f"(c[mt][nt][2]), "+f"(c[mt][nt][3])
                        : "r"(af[mt][0]), "r"(af[mt][1]), "r"(af[mt][2]), "r"(af[mt][3]),
                          "r"(bf[nt][0]), "r"(bf[nt][1]));
        }
        __syncthreads();
    }

    if (MODE == 0) {
        float* redS = (float*)sm;             // [4][128] overlay (compute done)
        float* redQ = (float*)(sm + 2048);    // [4][128]
        // LN per pixel: quad shfl + cross-warp smem reduce
#pragma unroll
        for (int mt = 0; mt < 4; mt++)
#pragma unroll
            for (int h = 0; h < 2; h++) {
                float su = 0.f, sq = 0.f;
#pragma unroll
                for (int nt = 0; nt < 8; nt++) {
                    float v0 = c[mt][nt][2 * h], v1 = c[mt][nt][2 * h + 1];
                    su += v0 + v1; sq += v0 * v0 + v1 * v1;
                }
                su += __shfl_xor_sync(0xffffffffu, su, 1);
                sq += __shfl_xor_sync(0xffffffffu, sq, 1);
                su += __shfl_xor_sync(0xffffffffu, su, 2);
                sq += __shfl_xor_sync(0xffffffffu, sq, 2);
                int px = wm * 64 + mt * 16 + g + 8 * h;
                if (l == 0) { redS[wn * 128 + px] = su; redQ[wn * 128 + px] = sq; }
            }
        __syncthreads();
#pragma unroll
        for (int mt = 0; mt < 4; mt++)
#pragma unroll
            for (int h = 0; h < 2; h++) {
                int px = wm * 64 + mt * 16 + g + 8 * h;
                float su = redS[px] + redS[128 + px] + redS[256 + px] + redS[384 + px];
                float sq = redQ[px] + redQ[128 + px] + redQ[256 + px] + redQ[384 + px];
                float mu = su * (1.f / 256.f);
                float rs = rsqrtf(sq * (1.f / 256.f) - mu * mu + 1e-6f);
                float* dst = &g_qT[(size_t)(mbase + px) * 256];
#pragma unroll
                for (int nt = 0; nt < 8; nt++) {
                    int ch = wn * 64 + nt * 8 + 2 * l;
                    float2 o2;
                    o2.x = (c[mt][nt][2*h]   - mu) * rs * gb[ch]   * 0.125f + gb[256+ch]   * 0.125f;
                    o2.y = (c[mt][nt][2*h+1] - mu) * rs * gb[ch+1] * 0.125f + gb[256+ch+1] * 0.125f;
                    *(float2*)&dst[ch] = o2;
                }
            }
    } else {
        // BN + channel-major store via smem transpose, 64-ch slabs
        const float rinv = rsqrtf(1.f + 1e-5f);
        const int b = mbase >> 12, n0 = mbase & 4095;
        float* stage = (float*)sm;   // [64][132] overlay
        for (int sl = 0; sl < 4; sl++) {
            __syncthreads();
            if (wn == sl) {
#pragma unroll
                for (int nt = 0; nt < 8; nt++) {
                    int cl = nt * 8 + 2 * l;
                    float gs0 = gb[sl*64 + cl] * rinv,     bs0 = gb[256 + sl*64 + cl];
                    float gs1 = gb[sl*64 + cl + 1] * rinv, bs1 = gb[256 + sl*64 + cl + 1];
#pragma unroll
                    for (int mt = 0; mt < 4; mt++) {
                        int px = wm * 64 + mt * 16 + g;
                        stage[cl * 132 + px]           = c[mt][nt][0] * gs0 + bs0;
                        stage[(cl + 1) * 132 + px]     = c[mt][nt][1] * gs1 + bs1;
                        stage[cl * 132 + px + 8]       = c[mt][nt][2] * gs0 + bs0;
                        stage[(cl + 1) * 132 + px + 8] = c[mt][nt][3] * gs1 + bs1;
                    }
                }
            }
            __syncthreads();
            int row = tid >> 2, seg = (tid & 3) * 32;
            float* dst = outp + (size_t)(b * 256 + sl * 64 + row) * 4096 + n0 + seg;
            const float* src = &stage[row * 132 + seg];
#pragma unroll
            for (int q = 0; q < 8; q++)
                *(float4*)&dst[q * 4] = *(const float4*)&src[q * 4];
        }
    }
}

// ---------------- K4: kf = LN(Wk @ kctx), per (b, l) ----------------
__global__ void __launch_bounds__(256) k_kfln(const float* __restrict__ gk,
                                              const float* __restrict__ bk) {
    __shared__ float kin[256];
    __shared__ float red[16];
    __shared__ float mu_s, rs_s;
    const int l = blockIdx.x, b = blockIdx.y, tid = threadIdx.x;
    kin[tid] = g_kctx[(b * 256 + tid) * 49 + l];
    __syncthreads();
    float acc = 0.f;
    for (int c = 0; c < 256; c++) acc += kin[c] * g_WkT[c * 256 + tid];
    float sum = acc, sq = acc * acc;
#pragma unroll
    for (int o = 16; o; o >>= 1) {
        sum += __shfl_xor_sync(0xffffffffu, sum, o);
        sq  += __shfl_xor_sync(0xffffffffu, sq,  o);
    }
    if ((tid & 31) == 0) { red[tid >> 5] = sum; red[8 + (tid >> 5)] = sq; }
    __syncthreads();
    if (tid == 0) {
        float S = 0.f, Q = 0.f;
#pragma unroll
        for (int w = 0; w < 8; w++) { S += red[w]; Q += red[8 + w]; }
        float mu = S * (1.f / 256.f);
        mu_s = mu;
        rs_s = rsqrtf(Q * (1.f / 256.f) - mu * mu + 1e-6f);
    }
    __syncthreads();
    g_kf[(b * 256 + tid) * 49 + l] = (acc - mu_s) * rs_s * gk[tid] + bk[tid];
}

// ---------------- K5: kp ----------------
__global__ void __launch_bounds__(256) k_kp(const float* __restrict__ Wproj) {
    int idx = blockIdx.x * 256 + threadIdx.x;
    int c = idx & 63;
    int rest = idx >> 6;
    int m = rest % 74;
    int bg = rest / 74;
    int ch = (bg & 3) * 64 + c;
    int b = bg >> 2;
    const float* kfrow = g_kf + (b * 256 + ch) * 49;
    const float* wrow = Wproj + m * 49;
    float s = 0.f;
#pragma unroll
    for (int l = 0; l < 49; l++) s += wrow[l] * kfrow[l];
    g_kp[idx] = s;
}

// ---------------- K6: logits + rpb + softmax + AV ----------------
template <int K>
__global__ void __launch_bounds__(256) k_attn(const float* __restrict__ rpb) {
    constexpr int MK = K * K;
    constexpr int RS = 2 * K - 1;
    constexpr int M0 = (K == 5) ? 0 : 25;
    const int g = blockIdx.y + ((K == 5) ? 0 : 2);
    const int b = blockIdx.z;
    const int i = blockIdx.x;
    const int tid = threadIdx.x;

    __shared__ __align__(16) float uni[7488];
    __shared__ float lg[64 * 50];
    __shared__ float rpbs[RS * RS];
    float* qs = uni;
    float* kps = uni + 64 * 68;
    const int bn = b * 4096;

    for (int idx = tid; idx < 64 * 16; idx += 256) {
        int j = idx >> 4, cc = idx & 15;
        *(float4*)&qs[j * 68 + cc * 4] =
            *(const float4*)&g_qT[(size_t)(bn + i * 64 + j) * 256 + g * 64 + cc * 4];
    }
    const float* kpbase = g_kp + ((b * 4 + g) * 74 + M0) * 64;
    for (int idx = tid; idx < MK * 16; idx += 256)
        *(float4*)&kps[idx * 4] = *(const float4*)&kpbase[idx * 4];
    for (int idx = tid; idx < RS * RS; idx += 256)
        rpbs[idx] = rpb[(g & 1) * RS * RS + idx];
    __syncthreads();

    {
        int j = tid & 63, mslot = tid >> 6;
        ull qp[32];
#pragma unroll
        for (int cc = 0; cc < 16; cc++) {
            ulonglong2 t = *(const ulonglong2*)&qs[j * 68 + cc * 4];
            qp[2 * cc] = t.x; qp[2 * cc + 1] = t.y;
        }
        for (int m = mslot; m < MK; m += 4) {
            ull a0 = 0ull, a1 = 0ull;
#pragma unroll
            for (int cc = 0; cc < 16; cc++) {
                ulonglong2 kv = *(const ulonglong2*)&kps[m * 64 + cc * 4];
                ffma2(a0, qp[2 * cc], kv.x);
                ffma2(a1, qp[2 * cc + 1], kv.y);
            }
            float2 fa = unpack2(a0), fb = unpack2(a1);
            lg[j * 50 + m] = (fa.x + fa.y) + (fb.x + fb.y);
        }
    }
    __syncthreads();

    const int si = min(max(i - K / 2, 0), 64 - K);
    const int j2 = tid >> 2, sub = tid & 3;
    const int sj = min(max(j2 - K / 2, 0), 64 - K);
    {
        int ro = (K - 1) - (i - si);
        int co = (K - 1) - (j2 - sj);
        float mx = -1e30f;
        for (int m = sub; m < MK; m += 4) {
            int p = m / K, q = m - p * K;
            float v = lg[j2 * 50 + m] + rpbs[(ro + p) * RS + (co + q)];
            lg[j2 * 50 + m] = v;
            mx = fmaxf(mx, v);
        }
        mx = fmaxf(mx, __shfl_xor_sync(0xffffffffu, mx, 1));
        mx = fmaxf(mx, __shfl_xor_sync(0xffffffffu, mx, 2));
        float s = 0.f;
        for (int m = sub; m < MK; m += 4) {
            float e = __expf(lg[j2 * 50 + m] - mx);
            lg[j2 * 50 + m] = e;
            s += e;
        }
        s += __shfl_xor_sync(0xffffffffu, s, 1);
        s += __shfl_xor_sync(0xffffffffu, s, 2);
        float inv = 1.f / s;
        for (int m = sub; m < MK; m += 4) lg[j2 * 50 + m] *= inv;
    }

    float4* vs4 = (float4*)uni;
    for (int cq = 0; cq < 4; cq++) {
        __syncthreads();
        for (int idx = tid; idx < K * 64 * 4; idx += 256) {
            int p = idx >> 8, col = (idx >> 2) & 63, c4 = idx & 3;
            vs4[idx] = *(const float4*)&g_xT[(size_t)(bn + (si + p) * 64 + col) * 256 +
                                             g * 64 + cq * 16 + c4 * 4];
        }
        __syncthreads();
        ull a0 = 0ull, a1 = 0ull;
#pragma unroll
        for (int p = 0; p < K; p++)
#pragma unroll
            for (int q = 0; q < K; q++) {
                float aw = lg[j2 * 50 + p * K + q];
                ull ap = pack2(aw, aw);
                ulonglong2 v2 = *(const ulonglong2*)&vs4[(p * 64 + sj + q) * 4 + sub];
                ffma2(a0, ap, v2.x);
                ffma2(a1, ap, v2.y);
            }
        float2 r0 = unpack2(a0), r1 = unpack2(a1);
        // write bf16 hi/lo split directly for the output GEMM
        const int oc = g * 64 + cq * 16 + sub * 4;
        const size_t px = (size_t)(bn + i * 64 + j2) * 512;
        __nv_bfloat16 h0 = __float2bfloat16(r0.x), h1 = __float2bfloat16(r0.y);
        __nv_bfloat16 h2 = __float2bfloat16(r1.x), h3 = __float2bfloat16(r1.y);
        __nv_bfloat162 ha, hb;
        ha.x = h0; ha.y = h1; hb.x = h2; hb.y = h3;
        *(__nv_bfloat162*)&g_avp[px + oc] = ha;
        *(__nv_bfloat162*)&g_avp[px + oc + 2] = hb;
        __nv_bfloat162 la, lb;
        la.x = __float2bfloat16(r0.x - __bfloat162float(h0));
        la.y = __float2bfloat16(r0.y - __bfloat162float(h1));
        lb.x = __float2bfloat16(r1.x - __bfloat162float(h2));
        lb.y = __float2bfloat16(r1.y - __bfloat162float(h3));
        *(__nv_bfloat162*)&g_avp[px + 256 + oc] = la;
        *(__nv_bfloat162*)&g_avp[px + 256 + oc + 2] = lb;
    }
}

// ---------------- launch ----------------
extern "C" void kernel_launch(void* const* d_in, const int* in_sizes, int n_in,
                              void* d_out, int out_size) {
    const float* x     = (const float*)d_in[0];
    const float* ctx   = (const float*)d_in[1];
    const float* Wq    = (const float*)d_in[2];
    const float* gq    = (const float*)d_in[3];
    const float* bq    = (const float*)d_in[4];
    const float* Wk    = (const float*)d_in[5];
    const float* gk    = (const float*)d_in[6];
    const float* bk    = (const float*)d_in[7];
    const float* Wproj = (const float*)d_in[8];
    const float* rpb1  = (const float*)d_in[9];
    const float* rpb2  = (const float*)d_in[10];
    const float* Wdy   = (const float*)d_in[11];
    const float* bn_g  = (const float*)d_in[12];
    const float* bn_b  = (const float*)d_in[13];
    float* out = (float*)d_out;

    const int GSMEM = 2 * STG + 2048;   // 63488
    cudaFuncSetAttribute(k_gemm<0>, cudaFuncAttributeMaxDynamicSharedMemorySize, GSMEM);
    cudaFuncSetAttribute(k_gemm<1>, cudaFuncAttributeMaxDynamicSharedMemorySize, GSMEM);

    dim3 b32(32, 8);
    // order arranged so the ncu capture slot (launch idx 3) hits k_gemm<0>
    k1_xt  <<<dim3(128, 8, 4), b32>>>(x);
    k_wexp <<<128, 256>>>(Wq, Wdy);
    k0_wt  <<<dim3(8, 8),      b32>>>(Wk);
    k_gemm<0><<<128, 256, GSMEM>>>(gq, bq, nullptr);
    k2_pool<<<196, 256>>>(ctx);
    k_kfln <<<dim3(49, 4), 256>>>(gk, bk);
    k_kp   <<<296, 256>>>(Wproj);
    k_attn<5><<<dim3(64, 2, 4), 256>>>(rpb1);
    k_attn<7><<<dim3(64, 2, 4), 256>>>(rpb2);
    k_gemm<1><<<128, 256, GSMEM>>>(bn_g, bn_b, out);
}

// round 12
// speedup vs baseline: 2.1315x; 1.0101x over previous
#include <cuda_runtime.h>
#include <cuda_bf16.h>
#include <cstdint>

#define BATCH 4
#define CDIM  256
#define NPIX  4096

typedef unsigned long long ull;

// ---------------- device-global scratch (no allocation allowed) ----------------
__device__ float g_WkT [CDIM*CDIM];
__device__ float g_xT  [BATCH*NPIX*CDIM];        // x pixel-major fp32 (attn V)
__device__ float g_qT  [BATCH*NPIX*CDIM];        // q pixel-major fp32
__device__ float g_kctx[BATCH*CDIM*49];
__device__ float g_kf  [BATCH*CDIM*49];
__device__ float g_kp  [BATCH*4*74*64];
__device__ __nv_bfloat16 g_xp [BATCH*NPIX*512];  // [px][ xh(256) | xl(256) ]
__device__ __nv_bfloat16 g_avp[BATCH*NPIX*512];  // [px][ ah(256) | al(256) ]
__device__ __nv_bfloat16 g_wqp[256*512];         // [o][ wh(256) | wl(256) ]
__device__ __nv_bfloat16 g_wdp[256*512];

// ---------------- helpers ----------------
__device__ __forceinline__ void ffma2(ull& d, ull a, ull b) {
    asm("fma.rn.f32x2 %0, %1, %2, %0;" : "+l"(d) : "l"(a), "l"(b));
}
__device__ __forceinline__ ull pack2(float lo, float hi) {
    ull r; asm("mov.b64 %0, {%1, %2};" : "=l"(r) : "f"(lo), "f"(hi)); return r;
}
__device__ __forceinline__ float2 unpack2(ull v) {
    float2 r; asm("mov.b64 {%0, %1}, %2;" : "=f"(r.x), "=f"(r.y) : "l"(v)); return r;
}
__device__ __forceinline__ void cp16(void* smem, const void* gmem) {
    unsigned s = (unsigned)__cvta_generic_to_shared(smem);
    asm volatile("cp.async.cg.shared.global [%0], [%1], 16;\n" :: "r"(s), "l"(gmem));
}
#define CP_COMMIT() asm volatile("cp.async.commit_group;\n" ::: "memory")
__device__ __forceinline__ void ldmx4(uint32_t* r, uint32_t addr) {
    asm volatile("ldmatrix.sync.aligned.m8n8.x4.shared.b16 {%0,%1,%2,%3}, [%4];"
        : "=r"(r[0]), "=r"(r[1]), "=r"(r[2]), "=r"(r[3]) : "r"(addr));
}

// ---------------- K0: transpose Wk only ----------------
__global__ void __launch_bounds__(256) k0_wt(const float* __restrict__ Wk) {
    __shared__ float t[32][33];
    int o0 = blockIdx.y * 32, c0 = blockIdx.x * 32;
    int tx = threadIdx.x, ty = threadIdx.y;
#pragma unroll
    for (int r = 0; r < 4; r++)
        t[ty + 8*r][tx] = Wk[(o0 + ty + 8*r) * 256 + c0 + tx];
    __syncthreads();
#pragma unroll
    for (int r = 0; r < 4; r++)
        g_WkT[(c0 + ty + 8*r) * 256 + o0 + tx] = t[tx][ty + 8*r];
}

// ---------------- K1: x -> g_xT (fp32) + g_xp (bf16 hi/lo) ----------------
__global__ void __launch_bounds__(256) k1_xt(const float* __restrict__ x) {
    __shared__ float t[32][33];
    int b = blockIdx.z, n0 = blockIdx.x * 32, c0 = blockIdx.y * 32;
    int tx = threadIdx.x, ty = threadIdx.y;
#pragma unroll
    for (int r = 0; r < 4; r++)
        t[ty + 8*r][tx] = x[(size_t)(b * 256 + c0 + ty + 8*r) * 4096 + n0 + tx];
    __syncthreads();
#pragma unroll
    for (int r = 0; r < 4; r++) {
        int row = b * 4096 + n0 + ty + 8*r, col = c0 + tx;
        float v = t[tx][ty + 8*r];
        g_xT[(size_t)row * 256 + col] = v;
        __nv_bfloat16 h = __float2bfloat16(v);
        g_xp[(size_t)row * 512 + col] = h;
        g_xp[(size_t)row * 512 + 256 + col] = __float2bfloat16(v - __bfloat162float(h));
    }
}

// ---------------- K2: ctx 8x8 mean pool ----------------
__global__ void __launch_bounds__(256) k2_pool(const float* __restrict__ ctx) {
    int idx = blockIdx.x * 256 + threadIdx.x;
    int l = idx % 49;
    int c = (idx / 49) & 255;
    int b = idx / (49 * 256);
    int i = l / 7, j = l % 7;
    const float* base = ctx + ((size_t)(b * 256 + c) * 56 + i * 8) * 56 + j * 8;
    float s = 0.f;
#pragma unroll
    for (int p = 0; p < 8; p++)
#pragma unroll
        for (int q = 0; q < 8; q++)
            s += base[p * 56 + q];
    g_kctx[idx] = s * (1.f / 64.f);
}

// ---------------- K-wexp: Wq/Wdy -> bf16 hi/lo ([o][ hi | lo ]) ----------------
__global__ void __launch_bounds__(256) k_wexp(const float* __restrict__ Wq,
                                              const float* __restrict__ Wdy) {
    int idx = blockIdx.x * 256 + threadIdx.x;          // 32768 total
    int sel = idx >> 14;
    int i2 = idx & 16383;
    int o = i2 >> 6, c = (i2 & 63) * 4;
    const float* W = sel ? Wdy : Wq;
    __nv_bfloat16* D = sel ? g_wdp : g_wqp;
    float4 v = *(const float4*)&W[o * 256 + c];
    __nv_bfloat16 h0 = __float2bfloat16(v.x), h1 = __float2bfloat16(v.y);
    __nv_bfloat16 h2 = __float2bfloat16(v.z), h3 = __float2bfloat16(v.w);
    __nv_bfloat162 a, bb;
    a.x = h0; a.y = h1; bb.x = h2; bb.y = h3;
    *(__nv_bfloat162*)&D[o * 512 + c] = a;
    *(__nv_bfloat162*)&D[o * 512 + c + 2] = bb;
    __nv_bfloat162 la, lb;
    la.x = __float2bfloat16(v.x - __bfloat162float(h0));
    la.y = __float2bfloat16(v.y - __bfloat162float(h1));
    lb.x = __float2bfloat16(v.z - __bfloat162float(h2));
    lb.y = __float2bfloat16(v.w - __bfloat162float(h3));
    *(__nv_bfloat162*)&D[o * 512 + 256 + c] = la;
    *(__nv_bfloat162*)&D[o * 512 + 256 + c + 2] = lb;
}

// ======== mma.sync split-bf16 GEMM: D[128 px, 256 o] = A @ B^T, K'=768 ========
// ldmatrix fragments + cp.async 3-stage pipeline, 1 sync/iter, hoisted frags.
// MODE 0: fused LN*SCALE -> g_qT (px-major). MODE 1: fused BN -> outp (ch-major).
#define STG 30720
template <int MODE>
__global__ void __launch_bounds__(256) k_gemm(const float* __restrict__ s0,
                                              const float* __restrict__ s1,
                                              float* __restrict__ outp) {
    extern __shared__ __align__(16) unsigned char sm[];   // 3*30720 + 2048
    float* gb = (float*)(sm + 3 * STG);                   // [512]

    const int tid = threadIdx.x, wid = tid >> 5, lane = tid & 31;
    const int wm = wid >> 2, wn = wid & 3;
    const int g = lane >> 2, l = lane & 3;
    const int mbase = blockIdx.x * 128;
    const __nv_bfloat16* Ag = (MODE == 0) ? g_xp : g_avp;
    const __nv_bfloat16* Bg = (MODE == 0) ? g_wqp : g_wdp;

    gb[tid] = s0[tid];
    gb[256 + tid] = s1[tid];

    float c[4][8][4];
#pragma unroll
    for (int mt = 0; mt < 4; mt++)
#pragma unroll
        for (int nt = 0; nt < 8; nt++)
#pragma unroll
            for (int q = 0; q < 4; q++) c[mt][nt][q] = 0.f;

    // ldmatrix per-lane base addresses
    const uint32_t smem_u32 = (uint32_t)__cvta_generic_to_shared(sm);
    const uint32_t aBase = smem_u32 +
        (uint32_t)((wm * 64 + ((lane >> 3) & 1) * 8 + (lane & 7)) * 80 + (lane >> 4) * 16);
    const uint32_t bBase = smem_u32 + 10240u +
        (uint32_t)((wn * 64 + ((lane >> 4) & 1) * 8 + (lane & 7)) * 80 + ((lane >> 3) & 1) * 16);

    // issue chunk cc into buffer bb (one cp.async group)
    auto issue = [&](int cc, int bb) {
        const int pr = cc >> 3, kc = (cc & 7) * 32;
        const int selA = (pr == 2) ? 256 : 0;      // products: hh, hl, lh
        const int selB = (pr == 1) ? 256 : 0;
        unsigned char* base = sm + bb * STG;
#pragma unroll
        for (int r = 0; r < 2; r++) {
            int s2 = tid * 2 + r, p = s2 >> 2, j = s2 & 3;
            cp16(base + p * 80 + j * 16,
                 &Ag[(size_t)(mbase + p) * 512 + selA + kc + j * 8]);
        }
#pragma unroll
        for (int j = 0; j < 4; j++)
            cp16(base + 10240 + tid * 80 + j * 16,
                 &Bg[(size_t)tid * 512 + selB + kc + j * 8]);
        CP_COMMIT();
    };

    // prologue: chunks 0 and 1
    issue(0, 0);
    issue(1, 1);

    int buf = 0;
    for (int it = 0; it < 24; it++) {
        if (it < 23)
            asm volatile("cp.async.wait_group 1;\n" ::: "memory");
        else
            asm volatile("cp.async.wait_group 0;\n" ::: "memory");
        __syncthreads();   // all warps done with compute(it-1); buffer (it+2)%3 free
        if (it + 2 < 24) {
            int nb = buf + 2; if (nb >= 3) nb -= 3;
            issue(it + 2, nb);
        }
        const uint32_t stOff = (uint32_t)(buf * STG);
        // hoist ALL fragment loads (both k-steps) ahead of the mma burst
        uint32_t af[2][4][4], bf[2][8][2];
#pragma unroll
        for (int s = 0; s < 2; s++) {
#pragma unroll
            for (int mt = 0; mt < 4; mt++)
                ldmx4(af[s][mt], aBase + stOff + (uint32_t)(mt * 16 * 80 + s * 32));
#pragma unroll
            for (int p = 0; p < 4; p++) {
                uint32_t r[4];
                ldmx4(r, bBase + stOff + (uint32_t)(p * 16 * 80 + s * 32));
                bf[s][2*p][0] = r[0]; bf[s][2*p][1] = r[1];
                bf[s][2*p+1][0] = r[2]; bf[s][2*p+1][1] = r[3];
            }
        }
#pragma unroll
        for (int s = 0; s < 2; s++)
#pragma unroll
            for (int nt = 0; nt < 8; nt++)
#pragma unroll
                for (int mt = 0; mt < 4; mt++)
                    asm("mma.sync.aligned.m16n8k16.row.col.f32.bf16.bf16.f32 "
                        "{%0,%1,%2,%3}, {%4,%5,%6,%7}, {%8,%9}, {%0,%1,%2,%3};"
                        : "+f"(c[mt][nt][0]), "+f"(c[mt][nt][1]),
                          "+f"(c[mt][nt][2]), "+f"(c[mt][nt][3])
                        : "r"(af[s][mt][0]), "r"(af[s][mt][1]),
                          "r"(af[s][mt][2]), "r"(af[s][mt][3]),
                          "r"(bf[s][nt][0]), "r"(bf[s][nt][1]));
        buf++; if (buf >= 3) buf = 0;
    }
    __syncthreads();

    if (MODE == 0) {
        float* redS = (float*)sm;             // [4][128] overlay (compute done)
        float* redQ = (float*)(sm + 2048);    // [4][128]
        // LN per pixel: quad shfl + cross-warp smem reduce
#pragma unroll
        for (int mt = 0; mt < 4; mt++)
#pragma unroll
            for (int h = 0; h < 2; h++) {
                float su = 0.f, sq = 0.f;
#pragma unroll
                for (int nt = 0; nt < 8; nt++) {
                    float v0 = c[mt][nt][2 * h], v1 = c[mt][nt][2 * h + 1];
                    su += v0 + v1; sq += v0 * v0 + v1 * v1;
                }
                su += __shfl_xor_sync(0xffffffffu, su, 1);
                sq += __shfl_xor_sync(0xffffffffu, sq, 1);
                su += __shfl_xor_sync(0xffffffffu, su, 2);
                sq += __shfl_xor_sync(0xffffffffu, sq, 2);
                int px = wm * 64 + mt * 16 + g + 8 * h;
                if (l == 0) { redS[wn * 128 + px] = su; redQ[wn * 128 + px] = sq; }
            }
        __syncthreads();
#pragma unroll
        for (int mt = 0; mt < 4; mt++)
#pragma unroll
            for (int h = 0; h < 2; h++) {
                int px = wm * 64 + mt * 16 + g + 8 * h;
                float su = redS[px] + redS[128 + px] + redS[256 + px] + redS[384 + px];
                float sq = redQ[px] + redQ[128 + px] + redQ[256 + px] + redQ[384 + px];
                float mu = su * (1.f / 256.f);
                float rs = rsqrtf(sq * (1.f / 256.f) - mu * mu + 1e-6f);
                float* dst = &g_qT[(size_t)(mbase + px) * 256];
#pragma unroll
                for (int nt = 0; nt < 8; nt++) {
                    int ch = wn * 64 + nt * 8 + 2 * l;
                    float2 o2;
                    o2.x = (c[mt][nt][2*h]   - mu) * rs * gb[ch]   * 0.125f + gb[256+ch]   * 0.125f;
                    o2.y = (c[mt][nt][2*h+1] - mu) * rs * gb[ch+1] * 0.125f + gb[256+ch+1] * 0.125f;
                    *(float2*)&dst[ch] = o2;
                }
            }
    } else {
        // BN + channel-major store via smem transpose, 64-ch slabs
        const float rinv = rsqrtf(1.f + 1e-5f);
        const int b = mbase >> 12, n0 = mbase & 4095;
        float* stage = (float*)sm;   // [64][132] overlay
        for (int sl = 0; sl < 4; sl++) {
            __syncthreads();
            if (wn == sl) {
#pragma unroll
                for (int nt = 0; nt < 8; nt++) {
                    int cl = nt * 8 + 2 * l;
                    float gs0 = gb[sl*64 + cl] * rinv,     bs0 = gb[256 + sl*64 + cl];
                    float gs1 = gb[sl*64 + cl + 1] * rinv, bs1 = gb[256 + sl*64 + cl + 1];
#pragma unroll
                    for (int mt = 0; mt < 4; mt++) {
                        int px = wm * 64 + mt * 16 + g;
                        stage[cl * 132 + px]           = c[mt][nt][0] * gs0 + bs0;
                        stage[(cl + 1) * 132 + px]     = c[mt][nt][1] * gs1 + bs1;
                        stage[cl * 132 + px + 8]       = c[mt][nt][2] * gs0 + bs0;
                        stage[(cl + 1) * 132 + px + 8] = c[mt][nt][3] * gs1 + bs1;
                    }
                }
            }
            __syncthreads();
            int row = tid >> 2, seg = (tid & 3) * 32;
            float* dst = outp + (size_t)(b * 256 + sl * 64 + row) * 4096 + n0 + seg;
            const float* src = &stage[row * 132 + seg];
#pragma unroll
            for (int q = 0; q < 8; q++)
                *(float4*)&dst[q * 4] = *(const float4*)&src[q * 4];
        }
    }
}

// ---------------- K4: kf = LN(Wk @ kctx), per (b, l) ----------------
__global__ void __launch_bounds__(256) k_kfln(const float* __restrict__ gk,
                                              const float* __restrict__ bk) {
    __shared__ float kin[256];
    __shared__ float red[16];
    __shared__ float mu_s, rs_s;
    const int l = blockIdx.x, b = blockIdx.y, tid = threadIdx.x;
    kin[tid] = g_kctx[(b * 256 + tid) * 49 + l];
    __syncthreads();
    float acc = 0.f;
    for (int c = 0; c < 256; c++) acc += kin[c] * g_WkT[c * 256 + tid];
    float sum = acc, sq = acc * acc;
#pragma unroll
    for (int o = 16; o; o >>= 1) {
        sum += __shfl_xor_sync(0xffffffffu, sum, o);
        sq  += __shfl_xor_sync(0xffffffffu, sq,  o);
    }
    if ((tid & 31) == 0) { red[tid >> 5] = sum; red[8 + (tid >> 5)] = sq; }
    __syncthreads();
    if (tid == 0) {
        float S = 0.f, Q = 0.f;
#pragma unroll
        for (int w = 0; w < 8; w++) { S += red[w]; Q += red[8 + w]; }
        float mu = S * (1.f / 256.f);
        mu_s = mu;
        rs_s = rsqrtf(Q * (1.f / 256.f) - mu * mu + 1e-6f);
    }
    __syncthreads();
    g_kf[(b * 256 + tid) * 49 + l] = (acc - mu_s) * rs_s * gk[tid] + bk[tid];
}

// ---------------- K5: kp ----------------
__global__ void __launch_bounds__(256) k_kp(const float* __restrict__ Wproj) {
    int idx = blockIdx.x * 256 + threadIdx.x;
    int c = idx & 63;
    int rest = idx >> 6;
    int m = rest % 74;
    int bg = rest / 74;
    int ch = (bg & 3) * 64 + c;
    int b = bg >> 2;
    const float* kfrow = g_kf + (b * 256 + ch) * 49;
    const float* wrow = Wproj + m * 49;
    float s = 0.f;
#pragma unroll
    for (int l = 0; l < 49; l++) s += wrow[l] * kfrow[l];
    g_kp[idx] = s;
}

// ---------------- K6: logits + rpb + softmax + AV ----------------
template <int K>
__global__ void __launch_bounds__(256) k_attn(const float* __restrict__ rpb) {
    constexpr int MK = K * K;
    constexpr int RS = 2 * K - 1;
    constexpr int M0 = (K == 5) ? 0 : 25;
    const int g = blockIdx.y + ((K == 5) ? 0 : 2);
    const int b = blockIdx.z;
    const int i = blockIdx.x;
    const int tid = threadIdx.x;

    __shared__ __align__(16) float uni[7488];
    __shared__ float lg[64 * 50];
    __shared__ float rpbs[RS * RS];
    float* qs = uni;
    float* kps = uni + 64 * 68;
    const int bn = b * 4096;

    for (int idx = tid; idx < 64 * 16; idx += 256) {
        int j = idx >> 4, cc = idx & 15;
        *(float4*)&qs[j * 68 + cc * 4] =
            *(const float4*)&g_qT[(size_t)(bn + i * 64 + j) * 256 + g * 64 + cc * 4];
    }
    const float* kpbase = g_kp + ((b * 4 + g) * 74 + M0) * 64;
    for (int idx = tid; idx < MK * 16; idx += 256)
        *(float4*)&kps[idx * 4] = *(const float4*)&kpbase[idx * 4];
    for (int idx = tid; idx < RS * RS; idx += 256)
        rpbs[idx] = rpb[(g & 1) * RS * RS + idx];
    __syncthreads();

    {
        int j = tid & 63, mslot = tid >> 6;
        ull qp[32];
#pragma unroll
        for (int cc = 0; cc < 16; cc++) {
            ulonglong2 t = *(const ulonglong2*)&qs[j * 68 + cc * 4];
            qp[2 * cc] = t.x; qp[2 * cc + 1] = t.y;
        }
        for (int m = mslot; m < MK; m += 4) {
            ull a0 = 0ull, a1 = 0ull;
#pragma unroll
            for (int cc = 0; cc < 16; cc++) {
                ulonglong2 kv = *(const ulonglong2*)&kps[m * 64 + cc * 4];
                ffma2(a0, qp[2 * cc], kv.x);
                ffma2(a1, qp[2 * cc + 1], kv.y);
            }
            float2 fa = unpack2(a0), fb = unpack2(a1);
            lg[j * 50 + m] = (fa.x + fa.y) + (fb.x + fb.y);
        }
    }
    __syncthreads();

    const int si = min(max(i - K / 2, 0), 64 - K);
    const int j2 = tid >> 2, sub = tid & 3;
    const int sj = min(max(j2 - K / 2, 0), 64 - K);
    {
        int ro = (K - 1) - (i - si);
        int co = (K - 1) - (j2 - sj);
        float mx = -1e30f;
        for (int m = sub; m < MK; m += 4) {
            int p = m / K, q = m - p * K;
            float v = lg[j2 * 50 + m] + rpbs[(ro + p) * RS + (co + q)];
            lg[j2 * 50 + m] = v;
            mx = fmaxf(mx, v);
        }
        mx = fmaxf(mx, __shfl_xor_sync(0xffffffffu, mx, 1));
        mx = fmaxf(mx, __shfl_xor_sync(0xffffffffu, mx, 2));
        float s = 0.f;
        for (int m = sub; m < MK; m += 4) {
            float e = __expf(lg[j2 * 50 + m] - mx);
            lg[j2 * 50 + m] = e;
            s += e;
        }
        s += __shfl_xor_sync(0xffffffffu, s, 1);
        s += __shfl_xor_sync(0xffffffffu, s, 2);
        float inv = 1.f / s;
        for (int m = sub; m < MK; m += 4) lg[j2 * 50 + m] *= inv;
    }

    float4* vs4 = (float4*)uni;
    for (int cq = 0; cq < 4; cq++) {
        __syncthreads();
        for (int idx = tid; idx < K * 64 * 4; idx += 256) {
            int p = idx >> 8, col = (idx >> 2) & 63, c4 = idx & 3;
            vs4[idx] = *(const float4*)&g_xT[(size_t)(bn + (si + p) * 64 + col) * 256 +
                                             g * 64 + cq * 16 + c4 * 4];
        }
        __syncthreads();
        ull a0 = 0ull, a1 = 0ull;
#pragma unroll
        for (int p = 0; p < K; p++)
#pragma unroll
            for (int q = 0; q < K; q++) {
                float aw = lg[j2 * 50 + p * K + q];
                ull ap = pack2(aw, aw);
                ulonglong2 v2 = *(const ulonglong2*)&vs4[(p * 64 + sj + q) * 4 + sub];
                ffma2(a0, ap, v2.x);
                ffma2(a1, ap, v2.y);
            }
        float2 r0 = unpack2(a0), r1 = unpack2(a1);
        // write bf16 hi/lo split directly for the output GEMM
        const int oc = g * 64 + cq * 16 + sub * 4;
        const size_t px = (size_t)(bn + i * 64 + j2) * 512;
        __nv_bfloat16 h0 = __float2bfloat16(r0.x), h1 = __float2bfloat16(r0.y);
        __nv_bfloat16 h2 = __float2bfloat16(r1.x), h3 = __float2bfloat16(r1.y);
        __nv_bfloat162 ha, hb;
        ha.x = h0; ha.y = h1; hb.x = h2; hb.y = h3;
        *(__nv_bfloat162*)&g_avp[px + oc] = ha;
        *(__nv_bfloat162*)&g_avp[px + oc + 2] = hb;
        __nv_bfloat162 la, lb;
        la.x = __float2bfloat16(r0.x - __bfloat162float(h0));
        la.y = __float2bfloat16(r0.y - __bfloat162float(h1));
        lb.x = __float2bfloat16(r1.x - __bfloat162float(h2));
        lb.y = __float2bfloat16(r1.y - __bfloat162float(h3));
        *(__nv_bfloat162*)&g_avp[px + 256 + oc] = la;
        *(__nv_bfloat162*)&g_avp[px + 256 + oc + 2] = lb;
    }
}

// ---------------- launch ----------------
extern "C" void kernel_launch(void* const* d_in, const int* in_sizes, int n_in,
                              void* d_out, int out_size) {
    const float* x     = (const float*)d_in[0];
    const float* ctx   = (const float*)d_in[1];
    const float* Wq    = (const float*)d_in[2];
    const float* gq    = (const float*)d_in[3];
    const float* bq    = (const float*)d_in[4];
    const float* Wk    = (const float*)d_in[5];
    const float* gk    = (const float*)d_in[6];
    const float* bk    = (const float*)d_in[7];
    const float* Wproj = (const float*)d_in[8];
    const float* rpb1  = (const float*)d_in[9];
    const float* rpb2  = (const float*)d_in[10];
    const float* Wdy   = (const float*)d_in[11];
    const float* bn_g  = (const float*)d_in[12];
    const float* bn_b  = (const float*)d_in[13];
    float* out = (float*)d_out;

    const int GSMEM = 3 * STG + 2048;   // 94208
    cudaFuncSetAttribute(k_gemm<0>, cudaFuncAttributeMaxDynamicSharedMemorySize, GSMEM);
    cudaFuncSetAttribute(k_gemm<1>, cudaFuncAttributeMaxDynamicSharedMemorySize, GSMEM);

    dim3 b32(32, 8);
    // order arranged so the ncu capture slot hits k_gemm<0>
    k1_xt  <<<dim3(128, 8, 4), b32>>>(x);
    k_wexp <<<128, 256>>>(Wq, Wdy);
    k0_wt  <<<dim3(8, 8),      b32>>>(Wk);
    k_gemm<0><<<128, 256, GSMEM>>>(gq, bq, nullptr);
    k2_pool<<<196, 256>>>(ctx);
    k_kfln <<<dim3(49, 4), 256>>>(gk, bk);
    k_kp   <<<296, 256>>>(Wproj);
    k_attn<5><<<dim3(64, 2, 4), 256>>>(rpb1);
    k_attn<7><<<dim3(64, 2, 4), 256>>>(rpb2);
    k_gemm<1><<<128, 256, GSMEM>>>(bn_g, bn_b, out);
}

// round 13
// speedup vs baseline: 2.4355x; 1.1426x over previous
#include <cuda_runtime.h>
#include <cuda_bf16.h>
#include <cstdint>

#define BATCH 4
#define CDIM  256
#define NPIX  4096

typedef unsigned long long ull;

// ---------------- device-global scratch (no allocation allowed) ----------------
__device__ float g_WkT [CDIM*CDIM];
__device__ float g_xT  [BATCH*NPIX*CDIM];        // x pixel-major fp32 (attn V)
__device__ float g_qT  [BATCH*NPIX*CDIM];        // q pixel-major fp32
__device__ float g_kctx[BATCH*CDIM*49];
__device__ float g_kf  [BATCH*CDIM*49];
__device__ float g_kp  [BATCH*4*74*64];
// Pre-tiled smem-image operand buffers for the bulk-copy GEMM.
// A-class: [mb(128)][tile(16 = part*8 + kc)][128 rows x 80B]   (64B data + 16B pad)
// B-class: [tile(16)][256 rows x 80B]
__device__ __align__(128) unsigned char g_xpT [128*16*10240];
__device__ __align__(128) unsigned char g_avpT[128*16*10240];
__device__ __align__(128) unsigned char g_wqpT[16*20480];
__device__ __align__(128) unsigned char g_wdpT[16*20480];

// ---------------- helpers ----------------
__device__ __forceinline__ void ffma2(ull& d, ull a, ull b) {
    asm("fma.rn.f32x2 %0, %1, %2, %0;" : "+l"(d) : "l"(a), "l"(b));
}
__device__ __forceinline__ ull pack2(float lo, float hi) {
    ull r; asm("mov.b64 %0, {%1, %2};" : "=l"(r) : "f"(lo), "f"(hi)); return r;
}
__device__ __forceinline__ float2 unpack2(ull v) {
    float2 r; asm("mov.b64 {%0, %1}, %2;" : "=f"(r.x), "=f"(r.y) : "l"(v)); return r;
}
__device__ __forceinline__ void ldmx4(uint32_t* r, uint32_t addr) {
    asm volatile("ldmatrix.sync.aligned.m8n8.x4.shared.b16 {%0,%1,%2,%3}, [%4];"
        : "=r"(r[0]), "=r"(r[1]), "=r"(r[2]), "=r"(r[3]) : "r"(addr));
}
__device__ __forceinline__ void bulk_g2s(uint32_t smem_dst, const void* gsrc,
                                         uint32_t bytes, uint32_t mbar) {
    asm volatile(
        "cp.async.bulk.shared::cluster.global.mbarrier::complete_tx::bytes "
        "[%0], [%1], %2, [%3];"
        :: "r"(smem_dst), "l"(gsrc), "r"(bytes), "r"(mbar) : "memory");
}
__device__ __forceinline__ void mbar_wait(uint32_t mbar, uint32_t phase) {
    asm volatile(
        "{\n\t.reg .pred P;\n\t"
        "W_%=:\n\t"
        "mbarrier.try_wait.parity.acquire.cta.shared::cta.b64 P, [%0], %1, 0x989680;\n\t"
        "@P bra D_%=;\n\t"
        "bra W_%=;\n\t"
        "D_%=:\n\t}"
        :: "r"(mbar), "r"(phase) : "memory");
}

// ---------------- K0: transpose Wk only ----------------
__global__ void __launch_bounds__(256) k0_wt(const float* __restrict__ Wk) {
    __shared__ float t[32][33];
    int o0 = blockIdx.y * 32, c0 = blockIdx.x * 32;
    int tx = threadIdx.x, ty = threadIdx.y;
#pragma unroll
    for (int r = 0; r < 4; r++)
        t[ty + 8*r][tx] = Wk[(o0 + ty + 8*r) * 256 + c0 + tx];
    __syncthreads();
#pragma unroll
    for (int r = 0; r < 4; r++)
        g_WkT[(c0 + ty + 8*r) * 256 + o0 + tx] = t[tx][ty + 8*r];
}

// ---------------- K1: x -> g_xT (fp32) + tiled bf16 hi/lo images ----------------
__global__ void __launch_bounds__(256) k1_xt(const float* __restrict__ x) {
    __shared__ float t[32][33];
    int b = blockIdx.z, n0 = blockIdx.x * 32, c0 = blockIdx.y * 32;
    int tx = threadIdx.x, ty = threadIdx.y;
#pragma unroll
    for (int r = 0; r < 4; r++)
        t[ty + 8*r][tx] = x[(size_t)(b * 256 + c0 + ty + 8*r) * 4096 + n0 + tx];
    __syncthreads();
#pragma unroll
    for (int r = 0; r < 4; r++) {
        int row = b * 4096 + n0 + ty + 8*r, col = c0 + tx;
        float v = t[tx][ty + 8*r];
        g_xT[(size_t)row * 256 + col] = v;
        __nv_bfloat16 h = __float2bfloat16(v);
        __nv_bfloat16 lo = __float2bfloat16(v - __bfloat162float(h));
        size_t off = ((size_t)(row >> 7) * 16 + (col >> 5)) * 10240 +
                     (size_t)(row & 127) * 80 + (col & 31) * 2;
        *(__nv_bfloat16*)(g_xpT + off) = h;
        *(__nv_bfloat16*)(g_xpT + off + 8 * 10240) = lo;
    }
}

// ---------------- K2: ctx 8x8 mean pool ----------------
__global__ void __launch_bounds__(256) k2_pool(const float* __restrict__ ctx) {
    int idx = blockIdx.x * 256 + threadIdx.x;
    int l = idx % 49;
    int c = (idx / 49) & 255;
    int b = idx / (49 * 256);
    int i = l / 7, j = l % 7;
    const float* base = ctx + ((size_t)(b * 256 + c) * 56 + i * 8) * 56 + j * 8;
    float s = 0.f;
#pragma unroll
    for (int p = 0; p < 8; p++)
#pragma unroll
        for (int q = 0; q < 8; q++)
            s += base[p * 56 + q];
    g_kctx[idx] = s * (1.f / 64.f);
}

// ---------------- K-wexp: Wq/Wdy -> tiled bf16 hi/lo images ----------------
__global__ void __launch_bounds__(256) k_wexp(const float* __restrict__ Wq,
                                              const float* __restrict__ Wdy) {
    int idx = blockIdx.x * 256 + threadIdx.x;          // 32768 total
    int sel = idx >> 14;
    int i2 = idx & 16383;
    int o = i2 >> 6, c = (i2 & 63) * 4;
    const float* W = sel ? Wdy : Wq;
    unsigned char* D = sel ? g_wdpT : g_wqpT;
    float4 v = *(const float4*)&W[o * 256 + c];
    __nv_bfloat16 h0 = __float2bfloat16(v.x), h1 = __float2bfloat16(v.y);
    __nv_bfloat16 h2 = __float2bfloat16(v.z), h3 = __float2bfloat16(v.w);
    size_t off = (size_t)(c >> 5) * 20480 + (size_t)o * 80 + (c & 31) * 2;
    __nv_bfloat162 a, bb;
    a.x = h0; a.y = h1; bb.x = h2; bb.y = h3;
    *(__nv_bfloat162*)(D + off) = a;
    *(__nv_bfloat162*)(D + off + 4) = bb;
    __nv_bfloat162 la, lb;
    la.x = __float2bfloat16(v.x - __bfloat162float(h0));
    la.y = __float2bfloat16(v.y - __bfloat162float(h1));
    lb.x = __float2bfloat16(v.z - __bfloat162float(h2));
    lb.y = __float2bfloat16(v.w - __bfloat162float(h3));
    *(__nv_bfloat162*)(D + off + 8 * 20480) = la;
    *(__nv_bfloat162*)(D + off + 8 * 20480 + 4) = lb;
}

// ======== mma.sync split-bf16 GEMM, operands streamed by cp.async.bulk ========
// MODE 0: fused LN*SCALE -> g_qT (px-major). MODE 1: fused BN -> outp (ch-major).
#define STG 30720
#define MB_OFF (3 * STG + 2048)
template <int MODE>
__global__ void __launch_bounds__(256) k_gemm(const float* __restrict__ s0,
                                              const float* __restrict__ s1,
                                              float* __restrict__ outp) {
    extern __shared__ __align__(16) unsigned char sm[];   // 3*STG + 2048 + 64
    float* gb = (float*)(sm + 3 * STG);                   // [512]

    const int tid = threadIdx.x, wid = tid >> 5, lane = tid & 31;
    const int wm = wid >> 2, wn = wid & 3;
    const int g = lane >> 2, l = lane & 3;
    const int mbase = blockIdx.x * 128;
    const unsigned char* Ag = (MODE == 0) ? g_xpT : g_avpT;
    const unsigned char* Bg = (MODE == 0) ? g_wqpT : g_wdpT;

    gb[tid] = s0[tid];
    gb[256 + tid] = s1[tid];

    float c[4][8][4];
#pragma unroll
    for (int mt = 0; mt < 4; mt++)
#pragma unroll
        for (int nt = 0; nt < 8; nt++)
#pragma unroll
            for (int q = 0; q < 4; q++) c[mt][nt][q] = 0.f;

    const uint32_t smem_u32 = (uint32_t)__cvta_generic_to_shared(sm);
    const uint32_t mb0 = smem_u32 + MB_OFF;
    const uint32_t aBase = smem_u32 +
        (uint32_t)((wm * 64 + ((lane >> 3) & 1) * 8 + (lane & 7)) * 80 + (lane >> 4) * 16);
    const uint32_t bBase = smem_u32 + 10240u +
        (uint32_t)((wn * 64 + ((lane >> 4) & 1) * 8 + (lane & 7)) * 80 + ((lane >> 3) & 1) * 16);

    if (tid == 0) {
#pragma unroll
        for (int s = 0; s < 3; s++)
            asm volatile("mbarrier.init.shared.b64 [%0], 1;" :: "r"(mb0 + s * 8) : "memory");
        asm volatile("fence.proxy.async.shared::cta;" ::: "memory");
    }
    __syncthreads();

    // issue chunk cc into stage ss (2 bulk copies, 30720 bytes total)
    auto issue = [&](int cc, int ss) {
        const int pr = cc >> 3, kc = cc & 7;
        const int ap = (pr == 2) ? 1 : 0;       // products: hh, hl, lh
        const int bp = (pr == 1) ? 1 : 0;
        const uint32_t mba = mb0 + ss * 8;
        asm volatile("mbarrier.arrive.expect_tx.shared.b64 _, [%0], %1;"
                     :: "r"(mba), "r"(30720u) : "memory");
        bulk_g2s(smem_u32 + ss * STG,
                 Ag + ((size_t)blockIdx.x * 16 + ap * 8 + kc) * 10240, 10240u, mba);
        bulk_g2s(smem_u32 + ss * STG + 10240u,
                 Bg + (size_t)(bp * 8 + kc) * 20480, 20480u, mba);
    };

    if (tid == 0) { issue(0, 0); issue(1, 1); }

    int buf = 0;
    for (int it = 0; it < 24; it++) {
        mbar_wait(mb0 + buf * 8, (uint32_t)((it / 3) & 1));
        __syncthreads();   // everyone past wait; compute(it-1) done -> stage (it+2)%3 free
        if (tid == 0 && it + 2 < 24) {
            int nb = buf + 2; if (nb >= 3) nb -= 3;
            issue(it + 2, nb);
        }
        const uint32_t stOff = (uint32_t)(buf * STG);
        uint32_t af[2][4][4], bf[2][8][2];
#pragma unroll
        for (int s = 0; s < 2; s++) {
#pragma unroll
            for (int mt = 0; mt < 4; mt++)
                ldmx4(af[s][mt], aBase + stOff + (uint32_t)(mt * 16 * 80 + s * 32));
#pragma unroll
            for (int p = 0; p < 4; p++) {
                uint32_t r[4];
                ldmx4(r, bBase + stOff + (uint32_t)(p * 16 * 80 + s * 32));
                bf[s][2*p][0] = r[0]; bf[s][2*p][1] = r[1];
                bf[s][2*p+1][0] = r[2]; bf[s][2*p+1][1] = r[3];
            }
        }
#pragma unroll
        for (int s = 0; s < 2; s++)
#pragma unroll
            for (int nt = 0; nt < 8; nt++)
#pragma unroll
                for (int mt = 0; mt < 4; mt++)
                    asm("mma.sync.aligned.m16n8k16.row.col.f32.bf16.bf16.f32 "
                        "{%0,%1,%2,%3}, {%4,%5,%6,%7}, {%8,%9}, {%0,%1,%2,%3};"
                        : "+f"(c[mt][nt][0]), "+f"(c[mt][nt][1]),
                          "+f"(c[mt][nt][2]), "+f"(c[mt][nt][3])
                        : "r"(af[s][mt][0]), "r"(af[s][mt][1]),
                          "r"(af[s][mt][2]), "r"(af[s][mt][3]),
                          "r"(bf[s][nt][0]), "r"(bf[s][nt][1]));
        buf++; if (buf >= 3) buf = 0;
    }
    __syncthreads();

    if (MODE == 0) {
        float* redS = (float*)sm;             // [4][128] overlay (compute done)
        float* redQ = (float*)(sm + 2048);    // [4][128]
#pragma unroll
        for (int mt = 0; mt < 4; mt++)
#pragma unroll
            for (int h = 0; h < 2; h++) {
                float su = 0.f, sq = 0.f;
#pragma unroll
                for (int nt = 0; nt < 8; nt++) {
                    float v0 = c[mt][nt][2 * h], v1 = c[mt][nt][2 * h + 1];
                    su += v0 + v1; sq += v0 * v0 + v1 * v1;
                }
                su += __shfl_xor_sync(0xffffffffu, su, 1);
                sq += __shfl_xor_sync(0xffffffffu, sq, 1);
                su += __shfl_xor_sync(0xffffffffu, su, 2);
                sq += __shfl_xor_sync(0xffffffffu, sq, 2);
                int px = wm * 64 + mt * 16 + g + 8 * h;
                if (l == 0) { redS[wn * 128 + px] = su; redQ[wn * 128 + px] = sq; }
            }
        __syncthreads();
#pragma unroll
        for (int mt = 0; mt < 4; mt++)
#pragma unroll
            for (int h = 0; h < 2; h++) {
                int px = wm * 64 + mt * 16 + g + 8 * h;
                float su = redS[px] + redS[128 + px] + redS[256 + px] + redS[384 + px];
                float sq = redQ[px] + redQ[128 + px] + redQ[256 + px] + redQ[384 + px];
                float mu = su * (1.f / 256.f);
                float rs = rsqrtf(sq * (1.f / 256.f) - mu * mu + 1e-6f);
                float* dst = &g_qT[(size_t)(mbase + px) * 256];
#pragma unroll
                for (int nt = 0; nt < 8; nt++) {
                    int ch = wn * 64 + nt * 8 + 2 * l;
                    float2 o2;
                    o2.x = (c[mt][nt][2*h]   - mu) * rs * gb[ch]   * 0.125f + gb[256+ch]   * 0.125f;
                    o2.y = (c[mt][nt][2*h+1] - mu) * rs * gb[ch+1] * 0.125f + gb[256+ch+1] * 0.125f;
                    *(float2*)&dst[ch] = o2;
                }
            }
    } else {
        // BN + channel-major store via smem transpose, 64-ch slabs
        const float rinv = rsqrtf(1.f + 1e-5f);
        const int b = mbase >> 12, n0 = mbase & 4095;
        float* stage = (float*)sm;   // [64][132] overlay
        for (int sl = 0; sl < 4; sl++) {
            __syncthreads();
            if (wn == sl) {
#pragma unroll
                for (int nt = 0; nt < 8; nt++) {
                    int cl = nt * 8 + 2 * l;
                    float gs0 = gb[sl*64 + cl] * rinv,     bs0 = gb[256 + sl*64 + cl];
                    float gs1 = gb[sl*64 + cl + 1] * rinv, bs1 = gb[256 + sl*64 + cl + 1];
#pragma unroll
                    for (int mt = 0; mt < 4; mt++) {
                        int px = wm * 64 + mt * 16 + g;
                        stage[cl * 132 + px]           = c[mt][nt][0] * gs0 + bs0;
                        stage[(cl + 1) * 132 + px]     = c[mt][nt][1] * gs1 + bs1;
                        stage[cl * 132 + px + 8]       = c[mt][nt][2] * gs0 + bs0;
                        stage[(cl + 1) * 132 + px + 8] = c[mt][nt][3] * gs1 + bs1;
                    }
                }
            }
            __syncthreads();
            int row = tid >> 2, seg = (tid & 3) * 32;
            float* dst = outp + (size_t)(b * 256 + sl * 64 + row) * 4096 + n0 + seg;
            const float* src = &stage[row * 132 + seg];
#pragma unroll
            for (int q = 0; q < 8; q++)
                *(float4*)&dst[q * 4] = *(const float4*)&src[q * 4];
        }
    }
}

// ---------------- K4: kf = LN(Wk @ kctx), per (b, l) ----------------
__global__ void __launch_bounds__(256) k_kfln(const float* __restrict__ gk,
                                              const float* __restrict__ bk) {
    __shared__ float kin[256];
    __shared__ float red[16];
    __shared__ float mu_s, rs_s;
    const int l = blockIdx.x, b = blockIdx.y, tid = threadIdx.x;
    kin[tid] = g_kctx[(b * 256 + tid) * 49 + l];
    __syncthreads();
    float acc = 0.f;
    for (int c = 0; c < 256; c++) acc += kin[c] * g_WkT[c * 256 + tid];
    float sum = acc, sq = acc * acc;
#pragma unroll
    for (int o = 16; o; o >>= 1) {
        sum += __shfl_xor_sync(0xffffffffu, sum, o);
        sq  += __shfl_xor_sync(0xffffffffu, sq,  o);
    }
    if ((tid & 31) == 0) { red[tid >> 5] = sum; red[8 + (tid >> 5)] = sq; }
    __syncthreads();
    if (tid == 0) {
        float S = 0.f, Q = 0.f;
#pragma unroll
        for (int w = 0; w < 8; w++) { S += red[w]; Q += red[8 + w]; }
        float mu = S * (1.f / 256.f);
        mu_s = mu;
        rs_s = rsqrtf(Q * (1.f / 256.f) - mu * mu + 1e-6f);
    }
    __syncthreads();
    g_kf[(b * 256 + tid) * 49 + l] = (acc - mu_s) * rs_s * gk[tid] + bk[tid];
}

// ---------------- K5: kp ----------------
__global__ void __launch_bounds__(256) k_kp(const float* __restrict__ Wproj) {
    int idx = blockIdx.x * 256 + threadIdx.x;
    int c = idx & 63;
    int rest = idx >> 6;
    int m = rest % 74;
    int bg = rest / 74;
    int ch = (bg & 3) * 64 + c;
    int b = bg >> 2;
    const float* kfrow = g_kf + (b * 256 + ch) * 49;
    const float* wrow = Wproj + m * 49;
    float s = 0.f;
#pragma unroll
    for (int l = 0; l < 49; l++) s += wrow[l] * kfrow[l];
    g_kp[idx] = s;
}

// ---------------- K6: logits + rpb + softmax + AV ----------------
template <int K>
__global__ void __launch_bounds__(256) k_attn(const float* __restrict__ rpb) {
    constexpr int MK = K * K;
    constexpr int RS = 2 * K - 1;
    constexpr int M0 = (K == 5) ? 0 : 25;
    const int g = blockIdx.y + ((K == 5) ? 0 : 2);
    const int b = blockIdx.z;
    const int i = blockIdx.x;
    const int tid = threadIdx.x;

    __shared__ __align__(16) float uni[7488];
    __shared__ float lg[64 * 50];
    __shared__ float rpbs[RS * RS];
    float* qs = uni;
    float* kps = uni + 64 * 68;
    const int bn = b * 4096;

    for (int idx = tid; idx < 64 * 16; idx += 256) {
        int j = idx >> 4, cc = idx & 15;
        *(float4*)&qs[j * 68 + cc * 4] =
            *(const float4*)&g_qT[(size_t)(bn + i * 64 + j) * 256 + g * 64 + cc * 4];
    }
    const float* kpbase = g_kp + ((b * 4 + g) * 74 + M0) * 64;
    for (int idx = tid; idx < MK * 16; idx += 256)
        *(float4*)&kps[idx * 4] = *(const float4*)&kpbase[idx * 4];
    for (int idx = tid; idx < RS * RS; idx += 256)
        rpbs[idx] = rpb[(g & 1) * RS * RS + idx];
    __syncthreads();

    {
        int j = tid & 63, mslot = tid >> 6;
        ull qp[32];
#pragma unroll
        for (int cc = 0; cc < 16; cc++) {
            ulonglong2 t = *(const ulonglong2*)&qs[j * 68 + cc * 4];
            qp[2 * cc] = t.x; qp[2 * cc + 1] = t.y;
        }
        for (int m = mslot; m < MK; m += 4) {
            ull a0 = 0ull, a1 = 0ull;
#pragma unroll
            for (int cc = 0; cc < 16; cc++) {
                ulonglong2 kv = *(const ulonglong2*)&kps[m * 64 + cc * 4];
                ffma2(a0, qp[2 * cc], kv.x);
                ffma2(a1, qp[2 * cc + 1], kv.y);
            }
            float2 fa = unpack2(a0), fb = unpack2(a1);
            lg[j * 50 + m] = (fa.x + fa.y) + (fb.x + fb.y);
        }
    }
    __syncthreads();

    const int si = min(max(i - K / 2, 0), 64 - K);
    const int j2 = tid >> 2, sub = tid & 3;
    const int sj = min(max(j2 - K / 2, 0), 64 - K);
    {
        int ro = (K - 1) - (i - si);
        int co = (K - 1) - (j2 - sj);
        float mx = -1e30f;
        for (int m = sub; m < MK; m += 4) {
            int p = m / K, q = m - p * K;
            float v = lg[j2 * 50 + m] + rpbs[(ro + p) * RS + (co + q)];
            lg[j2 * 50 + m] = v;
            mx = fmaxf(mx, v);
        }
        mx = fmaxf(mx, __shfl_xor_sync(0xffffffffu, mx, 1));
        mx = fmaxf(mx, __shfl_xor_sync(0xffffffffu, mx, 2));
        float s = 0.f;
        for (int m = sub; m < MK; m += 4) {
            float e = __expf(lg[j2 * 50 + m] - mx);
            lg[j2 * 50 + m] = e;
            s += e;
        }
        s += __shfl_xor_sync(0xffffffffu, s, 1);
        s += __shfl_xor_sync(0xffffffffu, s, 2);
        float inv = 1.f / s;
        for (int m = sub; m < MK; m += 4) lg[j2 * 50 + m] *= inv;
    }

    float4* vs4 = (float4*)uni;
    for (int cq = 0; cq < 4; cq++) {
        __syncthreads();
        for (int idx = tid; idx < K * 64 * 4; idx += 256) {
            int p = idx >> 8, col = (idx >> 2) & 63, c4 = idx & 3;
            vs4[idx] = *(const float4*)&g_xT[(size_t)(bn + (si + p) * 64 + col) * 256 +
                                             g * 64 + cq * 16 + c4 * 4];
        }
        __syncthreads();
        ull a0 = 0ull, a1 = 0ull;
#pragma unroll
        for (int p = 0; p < K; p++)
#pragma unroll
            for (int q = 0; q < K; q++) {
                float aw = lg[j2 * 50 + p * K + q];
                ull ap = pack2(aw, aw);
                ulonglong2 v2 = *(const ulonglong2*)&vs4[(p * 64 + sj + q) * 4 + sub];
                ffma2(a0, ap, v2.x);
                ffma2(a1, ap, v2.y);
            }
        float2 r0 = unpack2(a0), r1 = unpack2(a1);
        // write bf16 hi/lo split directly into the tiled GEMM operand image
        const int oc = g * 64 + cq * 16 + sub * 4;
        const int pxr = i * 64 + j2;           // row within batch; mb = global px >> 7
        const size_t off = ((size_t)((bn + pxr) >> 7) * 16 + (oc >> 5)) * 10240 +
                           (size_t)(pxr & 127) * 80 + (oc & 31) * 2;
        __nv_bfloat16 h0 = __float2bfloat16(r0.x), h1 = __float2bfloat16(r0.y);
        __nv_bfloat16 h2 = __float2bfloat16(r1.x), h3 = __float2bfloat16(r1.y);
        __nv_bfloat162 ha, hb;
        ha.x = h0; ha.y = h1; hb.x = h2; hb.y = h3;
        *(__nv_bfloat162*)(g_avpT + off) = ha;
        *(__nv_bfloat162*)(g_avpT + off + 4) = hb;
        __nv_bfloat162 la, lb;
        la.x = __float2bfloat16(r0.x - __bfloat162float(h0));
        la.y = __float2bfloat16(r0.y - __bfloat162float(h1));
        lb.x = __float2bfloat16(r1.x - __bfloat162float(h2));
        lb.y = __float2bfloat16(r1.y - __bfloat162float(h3));
        *(__nv_bfloat162*)(g_avpT + off + 8 * 10240) = la;
        *(__nv_bfloat162*)(g_avpT + off + 8 * 10240 + 4) = lb;
    }
}

// ---------------- launch ----------------
extern "C" void kernel_launch(void* const* d_in, const int* in_sizes, int n_in,
                              void* d_out, int out_size) {
    const float* x     = (const float*)d_in[0];
    const float* ctx   = (const float*)d_in[1];
    const float* Wq    = (const float*)d_in[2];
    const float* gq    = (const float*)d_in[3];
    const float* bq    = (const float*)d_in[4];
    const float* Wk    = (const float*)d_in[5];
    const float* gk    = (const float*)d_in[6];
    const float* bk    = (const float*)d_in[7];
    const float* Wproj = (const float*)d_in[8];
    const float* rpb1  = (const float*)d_in[9];
    const float* rpb2  = (const float*)d_in[10];
    const float* Wdy   = (const float*)d_in[11];
    const float* bn_g  = (const float*)d_in[12];
    const float* bn_b  = (const float*)d_in[13];
    float* out = (float*)d_out;

    const int GSMEM = 3 * STG + 2048 + 64;   // 94272
    cudaFuncSetAttribute(k_gemm<0>, cudaFuncAttributeMaxDynamicSharedMemorySize, GSMEM);
    cudaFuncSetAttribute(k_gemm<1>, cudaFuncAttributeMaxDynamicSharedMemorySize, GSMEM);

    dim3 b32(32, 8);
    // order arranged so the ncu capture slot hits k_gemm<0>
    k1_xt  <<<dim3(128, 8, 4), b32>>>(x);
    k_wexp <<<128, 256>>>(Wq, Wdy);
    k0_wt  <<<dim3(8, 8),      b32>>>(Wk);
    k_gemm<0><<<128, 256, GSMEM>>>(gq, bq, nullptr);
    k2_pool<<<196, 256>>>(ctx);
    k_kfln <<<dim3(49, 4), 256>>>(gk, bk);
    k_kp   <<<296, 256>>>(Wproj);
    k_attn<5><<<dim3(64, 2, 4), 256>>>(rpb1);
    k_attn<7><<<dim3(64, 2, 4), 256>>>(rpb2);
    k_gemm<1><<<128, 256, GSMEM>>>(bn_g, bn_b, out);
}